// round 13
// baseline (speedup 1.0000x reference)
#include <cuda_runtime.h>
#include <math.h>
#include <stdint.h>

static constexpr long PX = 512L * 512;
static constexpr long O_S1    = 0;
static constexpr long O_S2    = O_S1    + 6 * PX;
static constexpr long O_S3    = O_S2    + 6 * (PX / 4);
static constexpr long O_S4    = O_S3    + 6 * (PX / 16);
static constexpr long O_MULTI = O_S4    + 6 * (PX / 64);
static constexpr long O_MS    = O_MULTI + 24 * PX;
static constexpr long O_C2    = O_MS    + 32 * PX;
static constexpr long O_C3    = O_C2    + 32 * PX;          // (2,32,256,256)
static constexpr long O_C4    = O_C3    + 64 * (PX / 4);    // (2,32,128,128)
static constexpr long O_C5    = O_C4    + 64 * (PX / 16);   // (2,32,64,64)
static constexpr long O_C6    = O_C5    + 64 * (PX / 64);   // (2,64,32,32)
static constexpr long O_C6U   = O_C6    + 128 * (PX / 256);
static constexpr long O_C6S   = O_C6U   + 128 * (PX / 64);
static constexpr long O_C6RE  = O_C6S   + 128 * (PX / 64);
static constexpr long O_C7C   = O_C6RE  + 128 * (PX / 16);
static constexpr long O_C7    = O_C7C   + 64 * (PX / 16);
static constexpr long O_C8C   = O_C7    + 64 * (PX / 4);
static constexpr long O_C8    = O_C8C   + 32 * (PX / 4);
static constexpr long O_C9    = O_C8    + 32 * PX;
static constexpr long O_H3    = O_C9    + 128 * PX;
static constexpr long O_H4    = O_H3    + 32 * PX;
static constexpr long O_HM    = O_H4    + 32 * PX;
static constexpr long O_ELT   = O_HM    + 32 * PX;
static constexpr long O_C10   = O_ELT   + 32 * PX;
static constexpr long O_U9    = O_C10   + 128 * PX;
static constexpr long O_U10   = O_U9    + 32768;
static constexpr long POOL_TOTAL = O_U10 + 16384;

__device__ float g_pool[POOL_TOTAL];

typedef unsigned long long ull;
__device__ __forceinline__ ull pk2(float lo, float hi) {
    ull r; asm("mov.b64 %0, {%1, %2};" : "=l"(r) : "f"(lo), "f"(hi)); return r;
}
__device__ __forceinline__ void upk2(float& lo, float& hi, ull v) {
    asm("mov.b64 {%0, %1}, %2;" : "=f"(lo), "=f"(hi) : "l"(v));
}
__device__ __forceinline__ ull fma2(ull a, ull b, ull c) {
    ull d; asm("fma.rn.f32x2 %0, %1, %2, %3;" : "=l"(d) : "l"(a), "l"(b), "l"(c)); return d;
}
__device__ __forceinline__ float max2f(float2 a) { return fmaxf(a.x, a.y); }

// ---------------- fp32 direct conv (vectorized; optional fused 2x2 maxpool) ----
// POOL=1: srcA is a raw (2H x 2W) tensor; conv consumes maxpool2(srcA) on the fly.
template <int K, int ACT, int CO, int XT, int POOL>
__global__ __launch_bounds__(128)
void conv2d_pk(const float* __restrict__ srcA, int ca,
               const float* __restrict__ srcB, int cb,
               float* __restrict__ dst, int cout,
               const float* __restrict__ w, const float* __restrict__ bias,
               int H, int W, int N, int nblk)
{
    extern __shared__ float w_s[];
    const int ctot = ca + cb;
    const int coG = (cout + CO - 1) / CO;
    int blk = blockIdx.x;
    int pblk = blk % nblk;
    int cog  = (blk / nblk) % coG;
    int n    = blk / (nblk * coG);
    int co0  = cog * CO;
    const int nw = ctot * K * K;
    for (int i = threadIdx.x; i < nw * CO; i += blockDim.x) {
        int e = i / CO, j = i - e * CO, co = co0 + j;
        w_s[i] = (co < cout) ? __ldg(w + (long)co * nw + e) : 0.0f;
    }
    __syncthreads();
    const int WXT = W / XT;
    int pos = pblk * blockDim.x + threadIdx.x;
    if (pos >= H * WXT) return;
    int y = pos / WXT, x0 = (pos % WXT) * XT;
    constexpr int P = K / 2, CP = CO / 2, NV = K + XT - 1;
    const int W2 = W * 2;
    ull acc[CP][XT];
#pragma unroll
    for (int cp = 0; cp < CP; ++cp) {
        float b0 = (co0 + 2 * cp < cout) ? __ldg(bias + co0 + 2 * cp) : 0.0f;
        float b1 = (co0 + 2 * cp + 1 < cout) ? __ldg(bias + co0 + 2 * cp + 1) : 0.0f;
        ull bp = pk2(b0, b1);
#pragma unroll
        for (int m = 0; m < XT; ++m) acc[cp][m] = bp;
    }
    bool lok[P], rok[K - 1 - P];
#pragma unroll
    for (int i = 0; i < P; ++i) lok[i] = (x0 - P + i >= 0);
#pragma unroll
    for (int i = 0; i < K - 1 - P; ++i) rok[i] = (x0 + XT + i < W);

    for (int ci = 0; ci < ctot; ++ci) {
        const float* plane = (ci < ca)
            ? srcA + ((long)n * ca + ci) * (POOL ? (long)H * W * 4 : (long)H * W)
            : srcB + ((long)n * cb + (ci - ca)) * (long)H * W;
        const float* ws = w_s + ci * (K * K * CO);
#pragma unroll
        for (int ky = 0; ky < K; ++ky) {
            int yy = y + ky - P;
            if (yy < 0 || yy >= H) continue;
            float vf[NV];
            if (POOL) {
                const float* r0 = plane + (long)(2 * yy) * W2 + 2 * x0;
                const float* r1 = r0 + W2;
#pragma unroll
                for (int q = 0; q < XT; ++q) {
                    float2 a = *reinterpret_cast<const float2*>(r0 + 2 * q);
                    float2 b = *reinterpret_cast<const float2*>(r1 + 2 * q);
                    vf[P + q] = fmaxf(max2f(a), max2f(b));
                }
#pragma unroll
                for (int i = 0; i < P; ++i) {
                    float v = 0.0f;
                    if (lok[i]) {
                        float2 a = *reinterpret_cast<const float2*>(r0 + 2 * (i - P));
                        float2 b = *reinterpret_cast<const float2*>(r1 + 2 * (i - P));
                        v = fmaxf(max2f(a), max2f(b));
                    }
                    vf[i] = v;
                }
#pragma unroll
                for (int i = 0; i < K - 1 - P; ++i) {
                    float v = 0.0f;
                    if (rok[i]) {
                        float2 a = *reinterpret_cast<const float2*>(r0 + 2 * (XT + i));
                        float2 b = *reinterpret_cast<const float2*>(r1 + 2 * (XT + i));
                        v = fmaxf(max2f(a), max2f(b));
                    }
                    vf[P + XT + i] = v;
                }
            } else {
                const float* rp = plane + (long)yy * W + x0;
#pragma unroll
                for (int q = 0; q < XT / 4; ++q) {
                    float4 t = *reinterpret_cast<const float4*>(rp + 4 * q);
                    vf[P + 4 * q]     = t.x;
                    vf[P + 4 * q + 1] = t.y;
                    vf[P + 4 * q + 2] = t.z;
                    vf[P + 4 * q + 3] = t.w;
                }
#pragma unroll
                for (int i = 0; i < P; ++i)
                    vf[i] = lok[i] ? __ldg(rp + i - P) : 0.0f;
#pragma unroll
                for (int i = 0; i < K - 1 - P; ++i)
                    vf[P + XT + i] = rok[i] ? __ldg(rp + XT + i) : 0.0f;
            }

            ull pv[NV];
#pragma unroll
            for (int i = 0; i < NV; ++i) pv[i] = pk2(vf[i], vf[i]);
#pragma unroll
            for (int kx = 0; kx < K; ++kx) {
                const float* we = ws + (ky * K + kx) * CO;
#pragma unroll
                for (int cp = 0; cp < CP; ++cp) {
                    ull wv = *reinterpret_cast<const ull*>(we + 2 * cp);
#pragma unroll
                    for (int m = 0; m < XT; ++m)
                        acc[cp][m] = fma2(wv, pv[kx + m], acc[cp][m]);
                }
            }
        }
    }
#pragma unroll
    for (int cp = 0; cp < CP; ++cp) {
        float o0[XT], o1[XT];
#pragma unroll
        for (int m = 0; m < XT; ++m) upk2(o0[m], o1[m], acc[cp][m]);
#pragma unroll
        for (int h = 0; h < 2; ++h) {
            int co = co0 + 2 * cp + h;
            if (co >= cout) break;
            float* ov = h ? o1 : o0;
#pragma unroll
            for (int m = 0; m < XT; ++m) {
                if (ACT == 1) ov[m] = fmaxf(ov[m], 0.f);
                else if (ACT == 2) ov[m] = tanhf(ov[m]);
            }
            long o = (((long)n * cout + co) * H + y) * W + x0;
#pragma unroll
            for (int q = 0; q < XT / 4; ++q)
                *reinterpret_cast<float4*>(dst + o + 4 * q) =
                    make_float4(ov[4 * q], ov[4 * q + 1], ov[4 * q + 2], ov[4 * q + 3]);
        }
    }
}

// ---------------- Winograd filter transform ----------------
__global__ void wino_filt(const float* __restrict__ w, float* __restrict__ Ut, int CIN)
{
    int idx = blockIdx.x * blockDim.x + threadIdx.x;
    if (idx >= 64 * CIN) return;
    int co = idx / CIN, ci = idx % CIN;
    const float* gp = w + (co * CIN + ci) * 9;
    float g[3][3];
#pragma unroll
    for (int i = 0; i < 3; ++i)
#pragma unroll
        for (int j = 0; j < 3; ++j) g[i][j] = __ldg(gp + i * 3 + j);
    float Gg[4][3];
#pragma unroll
    for (int c = 0; c < 3; ++c) {
        Gg[0][c] = g[0][c];
        Gg[1][c] = 0.5f * (g[0][c] + g[1][c] + g[2][c]);
        Gg[2][c] = 0.5f * (g[0][c] - g[1][c] + g[2][c]);
        Gg[3][c] = g[2][c];
    }
#pragma unroll
    for (int u = 0; u < 4; ++u) {
        float U0 = Gg[u][0];
        float U1 = 0.5f * (Gg[u][0] + Gg[u][1] + Gg[u][2]);
        float U2 = 0.5f * (Gg[u][0] - Gg[u][1] + Gg[u][2]);
        float U3 = Gg[u][2];
        Ut[((u * 4 + 0) * CIN + ci) * 64 + co] = U0;
        Ut[((u * 4 + 1) * CIN + ci) * 64 + co] = U1;
        Ut[((u * 4 + 2) * CIN + ci) * 64 + co] = U2;
        Ut[((u * 4 + 3) * CIN + ci) * 64 + co] = U3;
    }
}

// ---------------- Fused Winograd conv ----------------
template <int CIN, int ACT>
__global__ __launch_bounds__(512, 1)
void conv3_wino(const float* __restrict__ srcA, int ca,
                const float* __restrict__ srcB,
                const float* __restrict__ Ut,
                const float* __restrict__ bias,
                float* __restrict__ dst)
{
    extern __shared__ float sm[];
    float* RAW = sm;
    float* VS  = sm + CIN * 408;
    float* MS  = VS + CIN * 272;
    float* BS  = MS + 16896;
    const int tid = threadIdx.x;
    const int bx = blockIdx.x, by = blockIdx.y, n = blockIdx.z;
    if (tid < 64) BS[tid] = __ldg(bias + tid);

    for (int i = tid; i < CIN * 396; i += 512) {
        int c = i % 66, rr = (i / 66) % 6, ci = i / 396;
        int px = bx * 64 + c - 1, py = by * 4 + rr - 1;
        float v = 0.0f;
        if (px >= 0 && px < 512 && py >= 0 && py < 512) {
            const float* p = (ci < ca)
                ? srcA + ((long)(n * ca + ci) * 512 + py) * 512 + px
                : srcB + ((long)(n * (CIN - ca) + (ci - ca)) * 512 + py) * 512 + px;
            v = __ldg(p);
        }
        RAW[ci * 408 + rr * 68 + c] = v;
    }
    __syncthreads();

    ull Y[4][4];
#pragma unroll
    for (int k = 0; k < 4; ++k)
#pragma unroll
        for (int q = 0; q < 4; ++q) Y[k][q] = 0ULL;

    const int lane = tid & 31, wp = tid >> 5;
    const int gv = wp >> 2, coh = (wp >> 1) & 1, tlh = wp & 1;
    const int co0 = coh * 32 + (lane >> 3) * 8;
    const int tl0 = tlh * 32 + (lane & 7) * 4;
    const ull ONE2 = pk2(1.f, 1.f), NEG2 = pk2(-1.f, -1.f);
    const int ia_t[4] = {0, 1, 2, 1}, ib_t[4] = {2, 2, 1, 3};
    const float sb_t[4] = {-1.f, 1.f, -1.f, -1.f};
    const float f0_t[4] = {1.f, 1.f, 1.f, 0.f};
    const float f1_t[4] = {0.f, 1.f, -1.f, -1.f};

    auto v_compute = [&](int g) {
        const int ia = ia_t[g], ib = ib_t[g];
        const ull SB = pk2(sb_t[g], sb_t[g]);
        for (int idx = tid; idx < CIN * 64; idx += 512) {
            int tl = idx & 63, ci = idx >> 6;
            int tly = tl >> 5, tlx = tl & 31;
            const float* rb = RAW + ci * 408 + (tly * 2) * 68 + tlx * 2;
            ull e01 = fma2(*(const ull*)(rb + ib * 68), SB, *(const ull*)(rb + ia * 68));
            ull e23 = fma2(*(const ull*)(rb + ib * 68 + 2), SB, *(const ull*)(rb + ia * 68 + 2));
            float e0, e1, e2, e3;
            upk2(e0, e1, e01); upk2(e2, e3, e23);
            float* vb = VS + ci * 68 + tl;
            vb[0]            = e0 - e2;
            vb[CIN * 68]     = e1 + e2;
            vb[2 * CIN * 68] = e2 - e1;
            vb[3 * CIN * 68] = e1 - e3;
        }
    };

    v_compute(0);
    __syncthreads();

    for (int g = 0; g < 4; ++g) {
        {
            ull acc[4][4];
#pragma unroll
            for (int p = 0; p < 4; ++p)
#pragma unroll
                for (int t = 0; t < 4; ++t) acc[p][t] = 0ULL;
            const float* Ub = Ut + ((long)(g * 4 + gv) * CIN) * 64 + co0;
            const float* Vb = VS + gv * CIN * 68 + tl0;
#pragma unroll 4
            for (int ci = 0; ci < CIN; ++ci) {
                const ull* up = (const ull*)(Ub + ci * 64);
                ull u0 = up[0], u1 = up[1], u2 = up[2], u3 = up[3];
                float4 vv = *(const float4*)(Vb + ci * 68);
                ull p0 = pk2(vv.x, vv.x), p1 = pk2(vv.y, vv.y);
                ull p2 = pk2(vv.z, vv.z), p3 = pk2(vv.w, vv.w);
                acc[0][0] = fma2(u0, p0, acc[0][0]); acc[0][1] = fma2(u0, p1, acc[0][1]);
                acc[0][2] = fma2(u0, p2, acc[0][2]); acc[0][3] = fma2(u0, p3, acc[0][3]);
                acc[1][0] = fma2(u1, p0, acc[1][0]); acc[1][1] = fma2(u1, p1, acc[1][1]);
                acc[1][2] = fma2(u1, p2, acc[1][2]); acc[1][3] = fma2(u1, p3, acc[1][3]);
                acc[2][0] = fma2(u2, p0, acc[2][0]); acc[2][1] = fma2(u2, p1, acc[2][1]);
                acc[2][2] = fma2(u2, p2, acc[2][2]); acc[2][3] = fma2(u2, p3, acc[2][3]);
                acc[3][0] = fma2(u3, p0, acc[3][0]); acc[3][1] = fma2(u3, p1, acc[3][1]);
                acc[3][2] = fma2(u3, p2, acc[3][2]); acc[3][3] = fma2(u3, p3, acc[3][3]);
            }
#pragma unroll
            for (int t = 0; t < 4; ++t)
#pragma unroll
                for (int p = 0; p < 4; ++p)
                    *(ull*)(MS + (gv * 64 + tl0 + t) * 66 + co0 + 2 * p) = acc[p][t];
        }
        __syncthreads();
        {
            const ull F0 = pk2(f0_t[g], f0_t[g]);
            const ull F1 = pk2(f1_t[g], f1_t[g]);
            int tl = tid & 63, cpg = tid >> 6;
#pragma unroll
            for (int k = 0; k < 4; ++k) {
                int cp = cpg * 4 + k;
                const float* mb = MS + tl * 66 + 2 * cp;
                ull m0 = *(const ull*)(mb);
                ull m1 = *(const ull*)(mb + 4224);
                ull m2 = *(const ull*)(mb + 8448);
                ull m3 = *(const ull*)(mb + 12672);
                ull z0 = fma2(m2, ONE2, fma2(m1, ONE2, m0));
                ull z1 = fma2(m3, NEG2, fma2(m2, NEG2, m1));
                Y[k][0] = fma2(z0, F0, Y[k][0]);
                Y[k][1] = fma2(z1, F0, Y[k][1]);
                Y[k][2] = fma2(z0, F1, Y[k][2]);
                Y[k][3] = fma2(z1, F1, Y[k][3]);
            }
        }
        if (g < 3) v_compute(g + 1);
        __syncthreads();
    }
    {
        int tl = tid & 63, cpg = tid >> 6;
        int tly = tl >> 5, tlx = tl & 31;
#pragma unroll
        for (int k = 0; k < 4; ++k) {
            int cp = cpg * 4 + k;
            float b0 = BS[2 * cp], b1 = BS[2 * cp + 1];
#pragma unroll
            for (int i = 0; i < 2; ++i)
#pragma unroll
                for (int j = 0; j < 2; ++j) {
                    float v0, v1;
                    upk2(v0, v1, Y[k][i * 2 + j]);
                    v0 += b0; v1 += b1;
                    if (ACT == 1) { v0 = fmaxf(v0, 0.f); v1 = fmaxf(v1, 0.f); }
                    else          { v0 = tanhf(v0);      v1 = tanhf(v1); }
                    int py = by * 4 + tly * 2 + i;
                    int px = bx * 64 + tlx * 2 + j;
                    dst[((long)(n * 64 + 2 * cp) * 512 + py) * 512 + px]     = v0;
                    dst[((long)(n * 64 + 2 * cp + 1) * 512 + py) * 512 + px] = v1;
                }
        }
    }
}

// ---------------- pool / upsample ----------------
__global__ void maxpool_kernel(const float* __restrict__ src, float* __restrict__ dst,
                               int C, int Ho, int Wo, int N)
{
    long idx = (long)blockIdx.x * blockDim.x + threadIdx.x;
    long total = (long)N * C * Ho * Wo;
    if (idx >= total) return;
    int x = (int)(idx % Wo);  long t = idx / Wo;
    int y = (int)(t % Ho);    t /= Ho;
    int c = (int)(t % C);
    int n = (int)(t / C);
    int Hi = Ho * 2, Wi = Wo * 2;
    const float* p = src + (((long)n * C + c) * Hi + 2 * y) * Wi + 2 * x;
    dst[idx] = fmaxf(fmaxf(p[0], p[1]), fmaxf(p[Wi], p[Wi + 1]));
}

__global__ void upsample_kernel(const float* __restrict__ src, float* __restrict__ dst,
                                int C, int Hs, int Ws, int scale,
                                long sBS, long dBS, int N)
{
    int Hd = Hs * scale, Wd = Ws * scale;
    long idx = (long)blockIdx.x * blockDim.x + threadIdx.x;
    long total = (long)N * C * Hd * Wd;
    if (idx >= total) return;
    int x = (int)(idx % Wd);  long t = idx / Wd;
    int y = (int)(t % Hd);    t /= Hd;
    int c = (int)(t % C);
    int n = (int)(t / C);
    float inv = 1.0f / (float)scale;
    float fy = (y + 0.5f) * inv - 0.5f;
    float fx = (x + 0.5f) * inv - 0.5f;
    int y0 = (int)floorf(fy), x0 = (int)floorf(fx);
    float wy = fy - (float)y0, wx = fx - (float)x0;
    int y0c = min(max(y0, 0), Hs - 1), y1c = min(max(y0 + 1, 0), Hs - 1);
    int x0c = min(max(x0, 0), Ws - 1), x1c = min(max(x0 + 1, 0), Ws - 1);
    const float* p = src + n * sBS + (long)c * Hs * Ws;
    float v00 = p[(long)y0c * Ws + x0c], v01 = p[(long)y0c * Ws + x1c];
    float v10 = p[(long)y1c * Ws + x0c], v11 = p[(long)y1c * Ws + x1c];
    float v = (1.f - wy) * ((1.f - wx) * v00 + wx * v01)
            +        wy  * ((1.f - wx) * v10 + wx * v11);
    dst[n * dBS + ((long)c * Hd + y) * Wd + x] = v;
}

// ---------------- scans ----------------
__device__ __forceinline__ float warp_affine_prefix(float& A, float& B, int lane)
{
#pragma unroll
    for (int d = 1; d < 32; d <<= 1) {
        float Ap = __shfl_up_sync(0xffffffffu, A, d);
        float Bp = __shfl_up_sync(0xffffffffu, B, d);
        if (lane >= d) { B = fmaf(A, Bp, B); A *= Ap; }
    }
    float yin = __shfl_up_sync(0xffffffffu, B, 1);
    return (lane == 0) ? 0.0f : yin;
}

__global__ __launch_bounds__(256) void hscan_fused()
{
    int gw = (blockIdx.x * blockDim.x + threadIdx.x) >> 5;
    int lane = threadIdx.x & 31;
    int y = gw % 512;  int t = gw / 512;
    int c = t % 16;    int n = t / 16;
    long rowc = ((long)(n * 16 + c) * 512 + y) * 512;
    const float* a1 = g_pool + O_C9 + ((long)(n * 64 + c)      * 512 + y) * 512;
    const float* a2 = g_pool + O_C9 + ((long)(n * 64 + 32 + c) * 512 + y) * 512;
    const float* u  = g_pool + O_MS + rowc;
    float* hm = g_pool + O_HM + rowc;
    int x0 = lane * 16, mlane = 31 - lane;

    float a1v[16], ufv[16], h1v[16], h2v[16];
#pragma unroll
    for (int k = 0; k < 16; ++k) { a1v[k] = a1[x0 + k]; ufv[k] = u[x0 + k]; }
    float A = 1.f, B = 0.f;
#pragma unroll
    for (int k = 0; k < 16; ++k) {
        float av = a1v[k];
        B = fmaf(av, B, (1.f - av) * ufv[k]);
        A *= av;
    }
    float yv = warp_affine_prefix(A, B, lane);
#pragma unroll
    for (int k = 0; k < 16; ++k) {
        float av = a1v[k];
        yv = fmaf(av, yv, (1.f - av) * ufv[k]);
        h1v[k] = yv;
    }
    float u2v[16];
#pragma unroll
    for (int k = 0; k < 16; ++k)
        u2v[k] = __shfl_sync(0xffffffffu, ufv[15 - k], mlane);
    A = 1.f; B = 0.f;
#pragma unroll
    for (int k = 0; k < 16; ++k) {
        float av = a1v[k];
        B = fmaf(av, B, (1.f - av) * u2v[k]);
        A *= av;
    }
    yv = warp_affine_prefix(A, B, lane);
#pragma unroll
    for (int k = 0; k < 16; ++k) {
        float av = a1v[k];
        yv = fmaf(av, yv, (1.f - av) * u2v[k]);
        h2v[k] = yv;
    }
#pragma unroll
    for (int k = 0; k < 16; ++k) a1v[k] = a2[x0 + k];
    A = 1.f; B = 0.f;
#pragma unroll
    for (int k = 0; k < 16; ++k) {
        float av = a1v[k];
        B = fmaf(av, B, (1.f - av) * h1v[k]);
        A *= av;
    }
    yv = warp_affine_prefix(A, B, lane);
#pragma unroll
    for (int k = 0; k < 16; ++k) {
        float av = a1v[k];
        yv = fmaf(av, yv, (1.f - av) * h1v[k]);
        h1v[k] = yv;
    }
    float u6v[16];
#pragma unroll
    for (int k = 0; k < 16; ++k)
        u6v[k] = __shfl_sync(0xffffffffu, h2v[15 - k], mlane);
    A = 1.f; B = 0.f;
#pragma unroll
    for (int k = 0; k < 16; ++k) {
        float av = a1v[k];
        B = fmaf(av, B, (1.f - av) * u6v[k]);
        A *= av;
    }
    yv = warp_affine_prefix(A, B, lane);
#pragma unroll
    for (int k = 0; k < 16; ++k) {
        float av = a1v[k];
        yv = fmaf(av, yv, (1.f - av) * u6v[k]);
        hm[x0 + k] = fmaxf(h1v[k], yv);
    }
}

__global__ __launch_bounds__(256) void vscan34_blk()
{
    int blk = blockIdx.x;
    int strip = blk & 15;  int t = blk >> 4;
    int c = t & 15;        int n = t >> 4;
    int lx = threadIdx.x & 31, g = threadIdx.x >> 5;
    int x = strip * 32 + lx;
    const float* gx1 = g_pool + O_C9 + (long)(n * 64 + c)      * PX;
    const float* gy1 = g_pool + O_C9 + (long)(n * 64 + 16 + c) * PX;
    const float* u   = g_pool + O_MS + (long)(n * 16 + c) * PX;
    float* h3 = g_pool + O_H3 + (long)(n * 16 + c) * PX;
    float* h4 = g_pool + O_H4 + (long)(n * 16 + c) * PX;
    __shared__ float sA[8][33], s3[8][33], s4[8][33];
    int y0 = g << 6;
    float A = 1.f, B3 = 0.f, B4 = 0.f;
    for (int i = 0; i < 64; ++i) {
        int y = y0 + i;
        float av = (y == 0) ? gy1[x] : gx1[(long)y * 512 + x];
        float om = 1.f - av;
        B3 = fmaf(av, B3, om * u[(long)y * 512 + x]);
        B4 = fmaf(av, B4, om * u[(long)(511 - y) * 512 + x]);
        A *= av;
    }
    sA[g][lx] = A; s3[g][lx] = B3; s4[g][lx] = B4;
    __syncthreads();
    if (g == 0) {
        float p3 = 0.f, p4 = 0.f;
        for (int gg = 0; gg < 8; ++gg) {
            float a_ = sA[gg][lx], b3 = s3[gg][lx], b4 = s4[gg][lx];
            s3[gg][lx] = p3; s4[gg][lx] = p4;
            p3 = fmaf(a_, p3, b3); p4 = fmaf(a_, p4, b4);
        }
    }
    __syncthreads();
    float y3 = s3[g][lx], y4 = s4[g][lx];
    for (int i = 0; i < 64; ++i) {
        int y = y0 + i;
        float av = (y == 0) ? gy1[x] : gx1[(long)y * 512 + x];
        float om = 1.f - av;
        y3 = fmaf(av, y3, om * u[(long)y * 512 + x]);
        h3[(long)y * 512 + x] = y3;
        y4 = fmaf(av, y4, om * u[(long)(511 - y) * 512 + x]);
        h4[(long)y * 512 + x] = y4;
    }
}

__global__ __launch_bounds__(256) void vscan78_blk()
{
    int blk = blockIdx.x;
    int strip = blk & 15;  int t = blk >> 4;
    int c = t & 15;        int n = t >> 4;
    int lx = threadIdx.x & 31, g = threadIdx.x >> 5;
    int x = strip * 32 + lx;
    const float* a  = g_pool + O_C9 + (long)(n * 64 + 48 + c) * PX;
    const float* h3 = g_pool + O_H3 + (long)(n * 16 + c) * PX;
    const float* h4 = g_pool + O_H4 + (long)(n * 16 + c) * PX;
    const float* hm = g_pool + O_HM + (long)(n * 16 + c) * PX;
    float* elt = g_pool + O_ELT + (long)(n * 16 + c) * PX;
    __shared__ float sA[8][33], s7[8][33], s8[8][33];
    int y0 = g << 6;
    float A = 1.f, B7 = 0.f, B8 = 0.f;
    for (int i = 0; i < 64; ++i) {
        int y = y0 + i;
        float av = a[(long)y * 512 + x];
        float om = 1.f - av;
        B7 = fmaf(av, B7, om * h3[(long)y * 512 + x]);
        B8 = fmaf(av, B8, om * h4[(long)(511 - y) * 512 + x]);
        A *= av;
    }
    sA[g][lx] = A; s7[g][lx] = B7; s8[g][lx] = B8;
    __syncthreads();
    if (g == 0) {
        float p7 = 0.f, p8 = 0.f;
        for (int gg = 0; gg < 8; ++gg) {
            float a_ = sA[gg][lx], b7 = s7[gg][lx], b8 = s8[gg][lx];
            s7[gg][lx] = p7; s8[gg][lx] = p8;
            p7 = fmaf(a_, p7, b7); p8 = fmaf(a_, p8, b8);
        }
    }
    __syncthreads();
    float y7 = s7[g][lx], y8 = s8[g][lx];
    for (int i = 0; i < 64; ++i) {
        int y = y0 + i;
        float av = a[(long)y * 512 + x];
        float om = 1.f - av;
        y7 = fmaf(av, y7, om * h3[(long)y * 512 + x]);
        y8 = fmaf(av, y8, om * h4[(long)(511 - y) * 512 + x]);
        elt[(long)y * 512 + x] = fmaxf(hm[(long)y * 512 + x], fmaxf(y7, y8));
    }
}

// ---------------- launch ----------------
static inline int gs(long total, int bs) { return (int)((total + bs - 1) / bs); }

template <int K, int ACT, int CO, int XT, int POOL = 0>
static void launch_conv(const float* srcA, int ca, const float* srcB, int cb,
                        float* dst, int cout, const float* w, const float* b,
                        int H, int W, int N, cudaStream_t st = 0)
{
    const int BT = 128;
    int WXT = W / XT;
    int nblk = (H * WXT + BT - 1) / BT;
    int coG = (cout + CO - 1) / CO;
    int blocks = N * coG * nblk;
    int smem = (ca + cb) * K * K * CO * (int)sizeof(float);
    conv2d_pk<K, ACT, CO, XT, POOL><<<blocks, BT, smem, st>>>(srcA, ca, srcB, cb, dst, cout, w, b, H, W, N, nblk);
}

extern "C" void kernel_launch(void* const* d_in, const int* in_sizes, int n_in,
                              void* d_out, int out_size)
{
    const float* x    = (const float*)d_in[0];
    const float* w_s1 = (const float*)d_in[1];  const float* b_s1 = (const float*)d_in[2];
    const float* w_mc = (const float*)d_in[3];  const float* b_mc = (const float*)d_in[4];
    const float* w2   = (const float*)d_in[5];  const float* b2   = (const float*)d_in[6];
    const float* w3   = (const float*)d_in[7];  const float* b3   = (const float*)d_in[8];
    const float* w4   = (const float*)d_in[9];  const float* b4   = (const float*)d_in[10];
    const float* w5   = (const float*)d_in[11]; const float* b5   = (const float*)d_in[12];
    const float* w6   = (const float*)d_in[13]; const float* b6   = (const float*)d_in[14];
    const float* w6s  = (const float*)d_in[15]; const float* b6s  = (const float*)d_in[16];
    const float* w7   = (const float*)d_in[17]; const float* b7   = (const float*)d_in[18];
    const float* w8   = (const float*)d_in[19]; const float* b8   = (const float*)d_in[20];
    const float* w9   = (const float*)d_in[21]; const float* b9   = (const float*)d_in[22];
    const float* w10  = (const float*)d_in[23]; const float* b10  = (const float*)d_in[24];
    const float* w11  = (const float*)d_in[25]; const float* b11  = (const float*)d_in[26];
    float* out = (float*)d_out;

    float* pool = nullptr;
    cudaGetSymbolAddress((void**)&pool, g_pool);

    static const int SM9  = (32 * 408 + 32 * 272 + 16896 + 64) * 4;
    static const int SM10 = (16 * 408 + 16 * 272 + 16896 + 64) * 4;
    cudaFuncSetAttribute(conv3_wino<32, 2>, cudaFuncAttributeMaxDynamicSharedMemorySize, SM9);
    cudaFuncSetAttribute(conv3_wino<16, 1>, cudaFuncAttributeMaxDynamicSharedMemorySize, SM10);

    static cudaStream_t sideQ = nullptr;
    static cudaEvent_t evFork = nullptr, evJoin = nullptr, evC9 = nullptr, evVs = nullptr;
    if (!sideQ) {
        cudaStreamCreateWithFlags(&sideQ, cudaStreamNonBlocking);
        cudaEventCreateWithFlags(&evFork, cudaEventDisableTiming);
        cudaEventCreateWithFlags(&evJoin, cudaEventDisableTiming);
        cudaEventCreateWithFlags(&evC9, cudaEventDisableTiming);
        cudaEventCreateWithFlags(&evVs, cudaEventDisableTiming);
    }

    const int BS = 256;
    const int N = 2;

    // ---- fork: branch A (multi/ms pyramid + filter transforms) on sideQ ----
    cudaEventRecord(evFork, 0);
    cudaStreamWaitEvent(sideQ, evFork, 0);

    wino_filt<<<gs(64 * 32, BS), BS, 0, sideQ>>>(w9, pool + O_U9, 32);
    wino_filt<<<gs(64 * 16, BS), BS, 0, sideQ>>>(w10, pool + O_U10, 16);
    launch_conv<3, 0, 4, 8>(x, 3, nullptr, 0, pool + O_S1, 3, w_s1, b_s1, 512, 512, N, sideQ);
    maxpool_kernel<<<gs((long)N * 3 * 256 * 256, BS), BS, 0, sideQ>>>(pool + O_S1, pool + O_S2, 3, 256, 256, N);
    maxpool_kernel<<<gs((long)N * 3 * 128 * 128, BS), BS, 0, sideQ>>>(pool + O_S2, pool + O_S3, 3, 128, 128, N);
    maxpool_kernel<<<gs((long)N * 3 * 64 * 64, BS), BS, 0, sideQ>>>(pool + O_S3, pool + O_S4, 3, 64, 64, N);
    for (int n = 0; n < N; ++n)
        cudaMemcpyAsync(pool + O_MULTI + (long)n * 12 * PX, pool + O_S1 + (long)n * 3 * PX,
                        3 * PX * sizeof(float), cudaMemcpyDeviceToDevice, sideQ);
    upsample_kernel<<<gs((long)N * 3 * PX, BS), BS, 0, sideQ>>>(pool + O_S2, pool + O_MULTI + 3 * PX,
        3, 256, 256, 2, 3 * (PX / 4), 12 * PX, N);
    upsample_kernel<<<gs((long)N * 3 * PX, BS), BS, 0, sideQ>>>(pool + O_S3, pool + O_MULTI + 6 * PX,
        3, 128, 128, 4, 3 * (PX / 16), 12 * PX, N);
    upsample_kernel<<<gs((long)N * 3 * PX, BS), BS, 0, sideQ>>>(pool + O_S4, pool + O_MULTI + 9 * PX,
        3, 64, 64, 8, 3 * (PX / 64), 12 * PX, N);
    launch_conv<3, 0, 8, 8>(pool + O_MULTI, 12, nullptr, 0, pool + O_MS, 16, w_mc, b_mc, 512, 512, N, sideQ);
    cudaEventRecord(evJoin, sideQ);

    // ---- branch B: c2 + encoder (pool fused into convs) + decoder ----
    launch_conv<5, 1, 8, 4>(x, 3, nullptr, 0, pool + O_C2, 16, w2, b2, 512, 512, N);
    launch_conv<3, 1, 8, 8, 1>(pool + O_C2, 16, nullptr, 0, pool + O_C3, 32, w3, b3, 256, 256, N);
    launch_conv<3, 1, 8, 8, 1>(pool + O_C3, 32, nullptr, 0, pool + O_C4, 32, w4, b4, 128, 128, N);
    launch_conv<3, 1, 8, 4, 1>(pool + O_C4, 32, nullptr, 0, pool + O_C5, 32, w5, b5, 64, 64, N);
    launch_conv<3, 1, 8, 4, 1>(pool + O_C5, 32, nullptr, 0, pool + O_C6, 64, w6, b6, 32, 32, N);
    upsample_kernel<<<gs((long)N * 64 * 64 * 64, BS), BS>>>(pool + O_C6, pool + O_C6U,
        64, 32, 32, 2, 64L * 32 * 32, 64L * 64 * 64, N);
    launch_conv<3, 1, 8, 4>(pool + O_C6U, 64, nullptr, 0, pool + O_C6S, 64, w6s, b6s, 64, 64, N);
    upsample_kernel<<<gs((long)N * 64 * 128 * 128, BS), BS>>>(pool + O_C6S, pool + O_C6RE,
        64, 64, 64, 2, 64L * 64 * 64, 64L * 128 * 128, N);
    launch_conv<3, 1, 8, 8>(pool + O_C6RE, 64, pool + O_C4, 32, pool + O_C7C, 32, w7, b7, 128, 128, N);
    upsample_kernel<<<gs((long)N * 32 * 256 * 256, BS), BS>>>(pool + O_C7C, pool + O_C7,
        32, 128, 128, 2, 32L * 128 * 128, 32L * 256 * 256, N);
    launch_conv<3, 1, 8, 8>(pool + O_C7, 32, pool + O_C3, 32, pool + O_C8C, 16, w8, b8, 256, 256, N);
    upsample_kernel<<<gs((long)N * 16 * 512 * 512, BS), BS>>>(pool + O_C8C, pool + O_C8,
        16, 256, 256, 2, 16L * 256 * 256, 16L * 512 * 512, N);

    // ---- join: c9 needs U9 (A) + c8/c2 (B); scans need ms (A) ----
    cudaStreamWaitEvent(0, evJoin, 0);

    {
        dim3 grid(8, 128, N);
        conv3_wino<32, 2><<<grid, 512, SM9>>>(pool + O_C8, 16, pool + O_C2,
                                              pool + O_U9, b9, pool + O_C9);
    }
    // overlap hscan (default) with vscan34 (sideQ): disjoint outputs
    cudaEventRecord(evC9, 0);
    cudaStreamWaitEvent(sideQ, evC9, 0);
    vscan34_blk<<<512, 256, 0, sideQ>>>();
    cudaEventRecord(evVs, sideQ);
    hscan_fused<<<2048, 256>>>();
    cudaStreamWaitEvent(0, evVs, 0);
    vscan78_blk<<<512, 256>>>();
    {
        dim3 grid(8, 128, N);
        conv3_wino<16, 1><<<grid, 512, SM10>>>(pool + O_ELT, 16, nullptr,
                                               pool + O_U10, b10, pool + O_C10);
    }
    launch_conv<3, 1, 4, 8>(pool + O_C10, 64, nullptr, 0, out, 3, w11, b11, 512, 512, N);
}

// round 14
// speedup vs baseline: 1.1161x; 1.1161x over previous
#include <cuda_runtime.h>
#include <math.h>
#include <stdint.h>

static constexpr long PX = 512L * 512;
static constexpr long O_S1    = 0;
static constexpr long O_S2    = O_S1    + 6 * PX;
static constexpr long O_S3    = O_S2    + 6 * (PX / 4);
static constexpr long O_S4    = O_S3    + 6 * (PX / 16);
static constexpr long O_MULTI = O_S4    + 6 * (PX / 64);
static constexpr long O_MS    = O_MULTI + 24 * PX;
static constexpr long O_C2    = O_MS    + 32 * PX;
static constexpr long O_C2P   = O_C2    + 32 * PX;
static constexpr long O_C3    = O_C2P   + 32 * (PX / 4);
static constexpr long O_C3P   = O_C3    + 64 * (PX / 4);
static constexpr long O_C4    = O_C3P   + 64 * (PX / 16);
static constexpr long O_C4P   = O_C4    + 64 * (PX / 16);
static constexpr long O_C5    = O_C4P   + 64 * (PX / 64);
static constexpr long O_C5P   = O_C5    + 64 * (PX / 64);
static constexpr long O_C6    = O_C5P   + 64 * (PX / 256);
static constexpr long O_C6U   = O_C6    + 128 * (PX / 256);
static constexpr long O_C6S   = O_C6U   + 128 * (PX / 64);
static constexpr long O_C6RE  = O_C6S   + 128 * (PX / 64);
static constexpr long O_C7C   = O_C6RE  + 128 * (PX / 16);
static constexpr long O_C7    = O_C7C   + 64 * (PX / 16);
static constexpr long O_C8C   = O_C7    + 64 * (PX / 4);
static constexpr long O_C8    = O_C8C   + 32 * (PX / 4);
static constexpr long O_C9    = O_C8    + 32 * PX;
static constexpr long O_H3    = O_C9    + 128 * PX;
static constexpr long O_H4    = O_H3    + 32 * PX;
static constexpr long O_HM    = O_H4    + 32 * PX;
static constexpr long O_ELT   = O_HM    + 32 * PX;
static constexpr long O_C10   = O_ELT   + 32 * PX;
static constexpr long O_U9    = O_C10   + 128 * PX;
static constexpr long O_U10   = O_U9    + 32768;
static constexpr long POOL_TOTAL = O_U10 + 16384;

__device__ float g_pool[POOL_TOTAL];

typedef unsigned long long ull;
__device__ __forceinline__ ull pk2(float lo, float hi) {
    ull r; asm("mov.b64 %0, {%1, %2};" : "=l"(r) : "f"(lo), "f"(hi)); return r;
}
__device__ __forceinline__ void upk2(float& lo, float& hi, ull v) {
    asm("mov.b64 {%0, %1}, %2;" : "=f"(lo), "=f"(hi) : "l"(v));
}
__device__ __forceinline__ ull fma2(ull a, ull b, ull c) {
    ull d; asm("fma.rn.f32x2 %0, %1, %2, %3;" : "=l"(d) : "l"(a), "l"(b), "l"(c)); return d;
}

// ---------------- fp32 direct conv (vectorized interior loads) ----------------
template <int K, int ACT, int CO, int XT>
__global__ __launch_bounds__(128)
void conv2d_pk(const float* __restrict__ srcA, int ca,
               const float* __restrict__ srcB, int cb,
               float* __restrict__ dst, int cout,
               const float* __restrict__ w, const float* __restrict__ bias,
               int H, int W, int N, int nblk)
{
    extern __shared__ float w_s[];
    const int ctot = ca + cb;
    const int coG = (cout + CO - 1) / CO;
    int blk = blockIdx.x;
    int pblk = blk % nblk;
    int cog  = (blk / nblk) % coG;
    int n    = blk / (nblk * coG);
    int co0  = cog * CO;
    const int nw = ctot * K * K;
    for (int i = threadIdx.x; i < nw * CO; i += blockDim.x) {
        int e = i / CO, j = i - e * CO, co = co0 + j;
        w_s[i] = (co < cout) ? __ldg(w + (long)co * nw + e) : 0.0f;
    }
    __syncthreads();
    const int WXT = W / XT;
    int pos = pblk * blockDim.x + threadIdx.x;
    if (pos >= H * WXT) return;
    int y = pos / WXT, x0 = (pos % WXT) * XT;
    constexpr int P = K / 2, CP = CO / 2, NV = K + XT - 1;
    ull acc[CP][XT];
#pragma unroll
    for (int cp = 0; cp < CP; ++cp) {
        float b0 = (co0 + 2 * cp < cout) ? __ldg(bias + co0 + 2 * cp) : 0.0f;
        float b1 = (co0 + 2 * cp + 1 < cout) ? __ldg(bias + co0 + 2 * cp + 1) : 0.0f;
        ull bp = pk2(b0, b1);
#pragma unroll
        for (int m = 0; m < XT; ++m) acc[cp][m] = bp;
    }
    bool lok[P], rok[K - 1 - P];
#pragma unroll
    for (int i = 0; i < P; ++i) lok[i] = (x0 - P + i >= 0);
#pragma unroll
    for (int i = 0; i < K - 1 - P; ++i) rok[i] = (x0 + XT + i < W);

    for (int ci = 0; ci < ctot; ++ci) {
        const float* plane = (ci < ca)
            ? srcA + ((long)n * ca + ci) * H * W
            : srcB + ((long)n * cb + (ci - ca)) * H * W;
        const float* ws = w_s + ci * (K * K * CO);
#pragma unroll
        for (int ky = 0; ky < K; ++ky) {
            int yy = y + ky - P;
            if (yy < 0 || yy >= H) continue;
            const float* rp = plane + (long)yy * W + x0;
            float vf[NV];
#pragma unroll
            for (int q = 0; q < XT / 4; ++q) {
                float4 t = *reinterpret_cast<const float4*>(rp + 4 * q);
                vf[P + 4 * q]     = t.x;
                vf[P + 4 * q + 1] = t.y;
                vf[P + 4 * q + 2] = t.z;
                vf[P + 4 * q + 3] = t.w;
            }
#pragma unroll
            for (int i = 0; i < P; ++i)
                vf[i] = lok[i] ? __ldg(rp + i - P) : 0.0f;
#pragma unroll
            for (int i = 0; i < K - 1 - P; ++i)
                vf[P + XT + i] = rok[i] ? __ldg(rp + XT + i) : 0.0f;

            ull pv[NV];
#pragma unroll
            for (int i = 0; i < NV; ++i) pv[i] = pk2(vf[i], vf[i]);
#pragma unroll
            for (int kx = 0; kx < K; ++kx) {
                const float* we = ws + (ky * K + kx) * CO;
#pragma unroll
                for (int cp = 0; cp < CP; ++cp) {
                    ull wv = *reinterpret_cast<const ull*>(we + 2 * cp);
#pragma unroll
                    for (int m = 0; m < XT; ++m)
                        acc[cp][m] = fma2(wv, pv[kx + m], acc[cp][m]);
                }
            }
        }
    }
#pragma unroll
    for (int cp = 0; cp < CP; ++cp) {
        float o0[XT], o1[XT];
#pragma unroll
        for (int m = 0; m < XT; ++m) upk2(o0[m], o1[m], acc[cp][m]);
#pragma unroll
        for (int h = 0; h < 2; ++h) {
            int co = co0 + 2 * cp + h;
            if (co >= cout) break;
            float* ov = h ? o1 : o0;
#pragma unroll
            for (int m = 0; m < XT; ++m) {
                if (ACT == 1) ov[m] = fmaxf(ov[m], 0.f);
                else if (ACT == 2) ov[m] = tanhf(ov[m]);
            }
            long o = (((long)n * cout + co) * H + y) * W + x0;
#pragma unroll
            for (int q = 0; q < XT / 4; ++q)
                *reinterpret_cast<float4*>(dst + o + 4 * q) =
                    make_float4(ov[4 * q], ov[4 * q + 1], ov[4 * q + 2], ov[4 * q + 3]);
        }
    }
}

// ---------------- Winograd filter transform ----------------
__global__ void wino_filt(const float* __restrict__ w, float* __restrict__ Ut, int CIN)
{
    int idx = blockIdx.x * blockDim.x + threadIdx.x;
    if (idx >= 64 * CIN) return;
    int co = idx / CIN, ci = idx % CIN;
    const float* gp = w + (co * CIN + ci) * 9;
    float g[3][3];
#pragma unroll
    for (int i = 0; i < 3; ++i)
#pragma unroll
        for (int j = 0; j < 3; ++j) g[i][j] = __ldg(gp + i * 3 + j);
    float Gg[4][3];
#pragma unroll
    for (int c = 0; c < 3; ++c) {
        Gg[0][c] = g[0][c];
        Gg[1][c] = 0.5f * (g[0][c] + g[1][c] + g[2][c]);
        Gg[2][c] = 0.5f * (g[0][c] - g[1][c] + g[2][c]);
        Gg[3][c] = g[2][c];
    }
#pragma unroll
    for (int u = 0; u < 4; ++u) {
        float U0 = Gg[u][0];
        float U1 = 0.5f * (Gg[u][0] + Gg[u][1] + Gg[u][2]);
        float U2 = 0.5f * (Gg[u][0] - Gg[u][1] + Gg[u][2]);
        float U3 = Gg[u][2];
        Ut[((u * 4 + 0) * CIN + ci) * 64 + co] = U0;
        Ut[((u * 4 + 1) * CIN + ci) * 64 + co] = U1;
        Ut[((u * 4 + 2) * CIN + ci) * 64 + co] = U2;
        Ut[((u * 4 + 3) * CIN + ci) * 64 + co] = U3;
    }
}

// ---------------- Fused Winograd conv ----------------
template <int CIN, int ACT>
__global__ __launch_bounds__(512, 1)
void conv3_wino(const float* __restrict__ srcA, int ca,
                const float* __restrict__ srcB,
                const float* __restrict__ Ut,
                const float* __restrict__ bias,
                float* __restrict__ dst)
{
    extern __shared__ float sm[];
    float* RAW = sm;
    float* VS  = sm + CIN * 408;
    float* MS  = VS + CIN * 272;
    float* BS  = MS + 16896;
    const int tid = threadIdx.x;
    const int bx = blockIdx.x, by = blockIdx.y, n = blockIdx.z;
    if (tid < 64) BS[tid] = __ldg(bias + tid);

    for (int i = tid; i < CIN * 396; i += 512) {
        int c = i % 66, rr = (i / 66) % 6, ci = i / 396;
        int px = bx * 64 + c - 1, py = by * 4 + rr - 1;
        float v = 0.0f;
        if (px >= 0 && px < 512 && py >= 0 && py < 512) {
            const float* p = (ci < ca)
                ? srcA + ((long)(n * ca + ci) * 512 + py) * 512 + px
                : srcB + ((long)(n * (CIN - ca) + (ci - ca)) * 512 + py) * 512 + px;
            v = __ldg(p);
        }
        RAW[ci * 408 + rr * 68 + c] = v;
    }
    __syncthreads();

    ull Y[4][4];
#pragma unroll
    for (int k = 0; k < 4; ++k)
#pragma unroll
        for (int q = 0; q < 4; ++q) Y[k][q] = 0ULL;

    const int lane = tid & 31, wp = tid >> 5;
    const int gv = wp >> 2, coh = (wp >> 1) & 1, tlh = wp & 1;
    const int co0 = coh * 32 + (lane >> 3) * 8;
    const int tl0 = tlh * 32 + (lane & 7) * 4;
    const ull ONE2 = pk2(1.f, 1.f), NEG2 = pk2(-1.f, -1.f);
    const int ia_t[4] = {0, 1, 2, 1}, ib_t[4] = {2, 2, 1, 3};
    const float sb_t[4] = {-1.f, 1.f, -1.f, -1.f};
    const float f0_t[4] = {1.f, 1.f, 1.f, 0.f};
    const float f1_t[4] = {0.f, 1.f, -1.f, -1.f};

    auto v_compute = [&](int g) {
        const int ia = ia_t[g], ib = ib_t[g];
        const ull SB = pk2(sb_t[g], sb_t[g]);
        for (int idx = tid; idx < CIN * 64; idx += 512) {
            int tl = idx & 63, ci = idx >> 6;
            int tly = tl >> 5, tlx = tl & 31;
            const float* rb = RAW + ci * 408 + (tly * 2) * 68 + tlx * 2;
            ull e01 = fma2(*(const ull*)(rb + ib * 68), SB, *(const ull*)(rb + ia * 68));
            ull e23 = fma2(*(const ull*)(rb + ib * 68 + 2), SB, *(const ull*)(rb + ia * 68 + 2));
            float e0, e1, e2, e3;
            upk2(e0, e1, e01); upk2(e2, e3, e23);
            float* vb = VS + ci * 68 + tl;
            vb[0]            = e0 - e2;
            vb[CIN * 68]     = e1 + e2;
            vb[2 * CIN * 68] = e2 - e1;
            vb[3 * CIN * 68] = e1 - e3;
        }
    };

    v_compute(0);
    __syncthreads();

    for (int g = 0; g < 4; ++g) {
        {
            ull acc[4][4];
#pragma unroll
            for (int p = 0; p < 4; ++p)
#pragma unroll
                for (int t = 0; t < 4; ++t) acc[p][t] = 0ULL;
            const float* Ub = Ut + ((long)(g * 4 + gv) * CIN) * 64 + co0;
            const float* Vb = VS + gv * CIN * 68 + tl0;
#pragma unroll 4
            for (int ci = 0; ci < CIN; ++ci) {
                const ull* up = (const ull*)(Ub + ci * 64);
                ull u0 = up[0], u1 = up[1], u2 = up[2], u3 = up[3];
                float4 vv = *(const float4*)(Vb + ci * 68);
                ull p0 = pk2(vv.x, vv.x), p1 = pk2(vv.y, vv.y);
                ull p2 = pk2(vv.z, vv.z), p3 = pk2(vv.w, vv.w);
                acc[0][0] = fma2(u0, p0, acc[0][0]); acc[0][1] = fma2(u0, p1, acc[0][1]);
                acc[0][2] = fma2(u0, p2, acc[0][2]); acc[0][3] = fma2(u0, p3, acc[0][3]);
                acc[1][0] = fma2(u1, p0, acc[1][0]); acc[1][1] = fma2(u1, p1, acc[1][1]);
                acc[1][2] = fma2(u1, p2, acc[1][2]); acc[1][3] = fma2(u1, p3, acc[1][3]);
                acc[2][0] = fma2(u2, p0, acc[2][0]); acc[2][1] = fma2(u2, p1, acc[2][1]);
                acc[2][2] = fma2(u2, p2, acc[2][2]); acc[2][3] = fma2(u2, p3, acc[2][3]);
                acc[3][0] = fma2(u3, p0, acc[3][0]); acc[3][1] = fma2(u3, p1, acc[3][1]);
                acc[3][2] = fma2(u3, p2, acc[3][2]); acc[3][3] = fma2(u3, p3, acc[3][3]);
            }
#pragma unroll
            for (int t = 0; t < 4; ++t)
#pragma unroll
                for (int p = 0; p < 4; ++p)
                    *(ull*)(MS + (gv * 64 + tl0 + t) * 66 + co0 + 2 * p) = acc[p][t];
        }
        __syncthreads();
        {
            const ull F0 = pk2(f0_t[g], f0_t[g]);
            const ull F1 = pk2(f1_t[g], f1_t[g]);
            int tl = tid & 63, cpg = tid >> 6;
#pragma unroll
            for (int k = 0; k < 4; ++k) {
                int cp = cpg * 4 + k;
                const float* mb = MS + tl * 66 + 2 * cp;
                ull m0 = *(const ull*)(mb);
                ull m1 = *(const ull*)(mb + 4224);
                ull m2 = *(const ull*)(mb + 8448);
                ull m3 = *(const ull*)(mb + 12672);
                ull z0 = fma2(m2, ONE2, fma2(m1, ONE2, m0));
                ull z1 = fma2(m3, NEG2, fma2(m2, NEG2, m1));
                Y[k][0] = fma2(z0, F0, Y[k][0]);
                Y[k][1] = fma2(z1, F0, Y[k][1]);
                Y[k][2] = fma2(z0, F1, Y[k][2]);
                Y[k][3] = fma2(z1, F1, Y[k][3]);
            }
        }
        if (g < 3) v_compute(g + 1);
        __syncthreads();
    }
    {
        int tl = tid & 63, cpg = tid >> 6;
        int tly = tl >> 5, tlx = tl & 31;
#pragma unroll
        for (int k = 0; k < 4; ++k) {
            int cp = cpg * 4 + k;
            float b0 = BS[2 * cp], b1 = BS[2 * cp + 1];
#pragma unroll
            for (int i = 0; i < 2; ++i)
#pragma unroll
                for (int j = 0; j < 2; ++j) {
                    float v0, v1;
                    upk2(v0, v1, Y[k][i * 2 + j]);
                    v0 += b0; v1 += b1;
                    if (ACT == 1) { v0 = fmaxf(v0, 0.f); v1 = fmaxf(v1, 0.f); }
                    else          { v0 = tanhf(v0);      v1 = tanhf(v1); }
                    int py = by * 4 + tly * 2 + i;
                    int px = bx * 64 + tlx * 2 + j;
                    dst[((long)(n * 64 + 2 * cp) * 512 + py) * 512 + px]     = v0;
                    dst[((long)(n * 64 + 2 * cp + 1) * 512 + py) * 512 + px] = v1;
                }
        }
    }
}

// ---------------- pool / upsample ----------------
__global__ void maxpool_kernel(const float* __restrict__ src, float* __restrict__ dst,
                               int C, int Ho, int Wo, int N)
{
    long idx = (long)blockIdx.x * blockDim.x + threadIdx.x;
    long total = (long)N * C * Ho * Wo;
    if (idx >= total) return;
    int x = (int)(idx % Wo);  long t = idx / Wo;
    int y = (int)(t % Ho);    t /= Ho;
    int c = (int)(t % C);
    int n = (int)(t / C);
    int Hi = Ho * 2, Wi = Wo * 2;
    const float* p = src + (((long)n * C + c) * Hi + 2 * y) * Wi + 2 * x;
    dst[idx] = fmaxf(fmaxf(p[0], p[1]), fmaxf(p[Wi], p[Wi + 1]));
}

__global__ void upsample_kernel(const float* __restrict__ src, float* __restrict__ dst,
                                int C, int Hs, int Ws, int scale,
                                long sBS, long dBS, int N)
{
    int Hd = Hs * scale, Wd = Ws * scale;
    long idx = (long)blockIdx.x * blockDim.x + threadIdx.x;
    long total = (long)N * C * Hd * Wd;
    if (idx >= total) return;
    int x = (int)(idx % Wd);  long t = idx / Wd;
    int y = (int)(t % Hd);    t /= Hd;
    int c = (int)(t % C);
    int n = (int)(t / C);
    float inv = 1.0f / (float)scale;
    float fy = (y + 0.5f) * inv - 0.5f;
    float fx = (x + 0.5f) * inv - 0.5f;
    int y0 = (int)floorf(fy), x0 = (int)floorf(fx);
    float wy = fy - (float)y0, wx = fx - (float)x0;
    int y0c = min(max(y0, 0), Hs - 1), y1c = min(max(y0 + 1, 0), Hs - 1);
    int x0c = min(max(x0, 0), Ws - 1), x1c = min(max(x0 + 1, 0), Ws - 1);
    const float* p = src + n * sBS + (long)c * Hs * Ws;
    float v00 = p[(long)y0c * Ws + x0c], v01 = p[(long)y0c * Ws + x1c];
    float v10 = p[(long)y1c * Ws + x0c], v11 = p[(long)y1c * Ws + x1c];
    float v = (1.f - wy) * ((1.f - wx) * v00 + wx * v01)
            +        wy  * ((1.f - wx) * v10 + wx * v11);
    dst[n * dBS + ((long)c * Hd + y) * Wd + x] = v;
}

// ---------------- scans ----------------
__device__ __forceinline__ float warp_affine_prefix(float& A, float& B, int lane)
{
#pragma unroll
    for (int d = 1; d < 32; d <<= 1) {
        float Ap = __shfl_up_sync(0xffffffffu, A, d);
        float Bp = __shfl_up_sync(0xffffffffu, B, d);
        if (lane >= d) { B = fmaf(A, Bp, B); A *= Ap; }
    }
    float yin = __shfl_up_sync(0xffffffffu, B, 1);
    return (lane == 0) ? 0.0f : yin;
}

__global__ __launch_bounds__(256) void hscan_fused()
{
    int gw = (blockIdx.x * blockDim.x + threadIdx.x) >> 5;
    int lane = threadIdx.x & 31;
    int y = gw % 512;  int t = gw / 512;
    int c = t % 16;    int n = t / 16;
    long rowc = ((long)(n * 16 + c) * 512 + y) * 512;
    const float* a1 = g_pool + O_C9 + ((long)(n * 64 + c)      * 512 + y) * 512;
    const float* a2 = g_pool + O_C9 + ((long)(n * 64 + 32 + c) * 512 + y) * 512;
    const float* u  = g_pool + O_MS + rowc;
    float* hm = g_pool + O_HM + rowc;
    int x0 = lane * 16, mlane = 31 - lane;

    float a1v[16], ufv[16], h1v[16], h2v[16];
#pragma unroll
    for (int k = 0; k < 16; ++k) { a1v[k] = a1[x0 + k]; ufv[k] = u[x0 + k]; }
    float A = 1.f, B = 0.f;
#pragma unroll
    for (int k = 0; k < 16; ++k) {
        float av = a1v[k];
        B = fmaf(av, B, (1.f - av) * ufv[k]);
        A *= av;
    }
    float yv = warp_affine_prefix(A, B, lane);
#pragma unroll
    for (int k = 0; k < 16; ++k) {
        float av = a1v[k];
        yv = fmaf(av, yv, (1.f - av) * ufv[k]);
        h1v[k] = yv;
    }
    float u2v[16];
#pragma unroll
    for (int k = 0; k < 16; ++k)
        u2v[k] = __shfl_sync(0xffffffffu, ufv[15 - k], mlane);
    A = 1.f; B = 0.f;
#pragma unroll
    for (int k = 0; k < 16; ++k) {
        float av = a1v[k];
        B = fmaf(av, B, (1.f - av) * u2v[k]);
        A *= av;
    }
    yv = warp_affine_prefix(A, B, lane);
#pragma unroll
    for (int k = 0; k < 16; ++k) {
        float av = a1v[k];
        yv = fmaf(av, yv, (1.f - av) * u2v[k]);
        h2v[k] = yv;
    }
#pragma unroll
    for (int k = 0; k < 16; ++k) a1v[k] = a2[x0 + k];
    A = 1.f; B = 0.f;
#pragma unroll
    for (int k = 0; k < 16; ++k) {
        float av = a1v[k];
        B = fmaf(av, B, (1.f - av) * h1v[k]);
        A *= av;
    }
    yv = warp_affine_prefix(A, B, lane);
#pragma unroll
    for (int k = 0; k < 16; ++k) {
        float av = a1v[k];
        yv = fmaf(av, yv, (1.f - av) * h1v[k]);
        h1v[k] = yv;
    }
    float u6v[16];
#pragma unroll
    for (int k = 0; k < 16; ++k)
        u6v[k] = __shfl_sync(0xffffffffu, h2v[15 - k], mlane);
    A = 1.f; B = 0.f;
#pragma unroll
    for (int k = 0; k < 16; ++k) {
        float av = a1v[k];
        B = fmaf(av, B, (1.f - av) * u6v[k]);
        A *= av;
    }
    yv = warp_affine_prefix(A, B, lane);
#pragma unroll
    for (int k = 0; k < 16; ++k) {
        float av = a1v[k];
        yv = fmaf(av, yv, (1.f - av) * u6v[k]);
        hm[x0 + k] = fmaxf(h1v[k], yv);
    }
}

__global__ __launch_bounds__(256) void vscan34_blk()
{
    int blk = blockIdx.x;
    int strip = blk & 15;  int t = blk >> 4;
    int c = t & 15;        int n = t >> 4;
    int lx = threadIdx.x & 31, g = threadIdx.x >> 5;
    int x = strip * 32 + lx;
    const float* gx1 = g_pool + O_C9 + (long)(n * 64 + c)      * PX;
    const float* gy1 = g_pool + O_C9 + (long)(n * 64 + 16 + c) * PX;
    const float* u   = g_pool + O_MS + (long)(n * 16 + c) * PX;
    float* h3 = g_pool + O_H3 + (long)(n * 16 + c) * PX;
    float* h4 = g_pool + O_H4 + (long)(n * 16 + c) * PX;
    __shared__ float sA[8][33], s3[8][33], s4[8][33];
    int y0 = g << 6;
    float A = 1.f, B3 = 0.f, B4 = 0.f;
    for (int i = 0; i < 64; ++i) {
        int y = y0 + i;
        float av = (y == 0) ? gy1[x] : gx1[(long)y * 512 + x];
        float om = 1.f - av;
        B3 = fmaf(av, B3, om * u[(long)y * 512 + x]);
        B4 = fmaf(av, B4, om * u[(long)(511 - y) * 512 + x]);
        A *= av;
    }
    sA[g][lx] = A; s3[g][lx] = B3; s4[g][lx] = B4;
    __syncthreads();
    if (g == 0) {
        float p3 = 0.f, p4 = 0.f;
        for (int gg = 0; gg < 8; ++gg) {
            float a_ = sA[gg][lx], b3 = s3[gg][lx], b4 = s4[gg][lx];
            s3[gg][lx] = p3; s4[gg][lx] = p4;
            p3 = fmaf(a_, p3, b3); p4 = fmaf(a_, p4, b4);
        }
    }
    __syncthreads();
    float y3 = s3[g][lx], y4 = s4[g][lx];
    for (int i = 0; i < 64; ++i) {
        int y = y0 + i;
        float av = (y == 0) ? gy1[x] : gx1[(long)y * 512 + x];
        float om = 1.f - av;
        y3 = fmaf(av, y3, om * u[(long)y * 512 + x]);
        h3[(long)y * 512 + x] = y3;
        y4 = fmaf(av, y4, om * u[(long)(511 - y) * 512 + x]);
        h4[(long)y * 512 + x] = y4;
    }
}

__global__ __launch_bounds__(256) void vscan78_blk()
{
    int blk = blockIdx.x;
    int strip = blk & 15;  int t = blk >> 4;
    int c = t & 15;        int n = t >> 4;
    int lx = threadIdx.x & 31, g = threadIdx.x >> 5;
    int x = strip * 32 + lx;
    const float* a  = g_pool + O_C9 + (long)(n * 64 + 48 + c) * PX;
    const float* h3 = g_pool + O_H3 + (long)(n * 16 + c) * PX;
    const float* h4 = g_pool + O_H4 + (long)(n * 16 + c) * PX;
    const float* hm = g_pool + O_HM + (long)(n * 16 + c) * PX;
    float* elt = g_pool + O_ELT + (long)(n * 16 + c) * PX;
    __shared__ float sA[8][33], s7[8][33], s8[8][33];
    int y0 = g << 6;
    float A = 1.f, B7 = 0.f, B8 = 0.f;
    for (int i = 0; i < 64; ++i) {
        int y = y0 + i;
        float av = a[(long)y * 512 + x];
        float om = 1.f - av;
        B7 = fmaf(av, B7, om * h3[(long)y * 512 + x]);
        B8 = fmaf(av, B8, om * h4[(long)(511 - y) * 512 + x]);
        A *= av;
    }
    sA[g][lx] = A; s7[g][lx] = B7; s8[g][lx] = B8;
    __syncthreads();
    if (g == 0) {
        float p7 = 0.f, p8 = 0.f;
        for (int gg = 0; gg < 8; ++gg) {
            float a_ = sA[gg][lx], b7 = s7[gg][lx], b8 = s8[gg][lx];
            s7[gg][lx] = p7; s8[gg][lx] = p8;
            p7 = fmaf(a_, p7, b7); p8 = fmaf(a_, p8, b8);
        }
    }
    __syncthreads();
    float y7 = s7[g][lx], y8 = s8[g][lx];
    for (int i = 0; i < 64; ++i) {
        int y = y0 + i;
        float av = a[(long)y * 512 + x];
        float om = 1.f - av;
        y7 = fmaf(av, y7, om * h3[(long)y * 512 + x]);
        y8 = fmaf(av, y8, om * h4[(long)(511 - y) * 512 + x]);
        elt[(long)y * 512 + x] = fmaxf(hm[(long)y * 512 + x], fmaxf(y7, y8));
    }
}

// ---------------- launch ----------------
static inline int gs(long total, int bs) { return (int)((total + bs - 1) / bs); }

template <int K, int ACT, int CO, int XT>
static void launch_conv(const float* srcA, int ca, const float* srcB, int cb,
                        float* dst, int cout, const float* w, const float* b,
                        int H, int W, int N, cudaStream_t st = 0)
{
    const int BT = 128;
    int WXT = W / XT;
    int nblk = (H * WXT + BT - 1) / BT;
    int coG = (cout + CO - 1) / CO;
    int blocks = N * coG * nblk;
    int smem = (ca + cb) * K * K * CO * (int)sizeof(float);
    conv2d_pk<K, ACT, CO, XT><<<blocks, BT, smem, st>>>(srcA, ca, srcB, cb, dst, cout, w, b, H, W, N, nblk);
}

extern "C" void kernel_launch(void* const* d_in, const int* in_sizes, int n_in,
                              void* d_out, int out_size)
{
    const float* x    = (const float*)d_in[0];
    const float* w_s1 = (const float*)d_in[1];  const float* b_s1 = (const float*)d_in[2];
    const float* w_mc = (const float*)d_in[3];  const float* b_mc = (const float*)d_in[4];
    const float* w2   = (const float*)d_in[5];  const float* b2   = (const float*)d_in[6];
    const float* w3   = (const float*)d_in[7];  const float* b3   = (const float*)d_in[8];
    const float* w4   = (const float*)d_in[9];  const float* b4   = (const float*)d_in[10];
    const float* w5   = (const float*)d_in[11]; const float* b5   = (const float*)d_in[12];
    const float* w6   = (const float*)d_in[13]; const float* b6   = (const float*)d_in[14];
    const float* w6s  = (const float*)d_in[15]; const float* b6s  = (const float*)d_in[16];
    const float* w7   = (const float*)d_in[17]; const float* b7   = (const float*)d_in[18];
    const float* w8   = (const float*)d_in[19]; const float* b8   = (const float*)d_in[20];
    const float* w9   = (const float*)d_in[21]; const float* b9   = (const float*)d_in[22];
    const float* w10  = (const float*)d_in[23]; const float* b10  = (const float*)d_in[24];
    const float* w11  = (const float*)d_in[25]; const float* b11  = (const float*)d_in[26];
    float* out = (float*)d_out;

    float* pool = nullptr;
    cudaGetSymbolAddress((void**)&pool, g_pool);

    static const int SM9  = (32 * 408 + 32 * 272 + 16896 + 64) * 4;
    static const int SM10 = (16 * 408 + 16 * 272 + 16896 + 64) * 4;
    cudaFuncSetAttribute(conv3_wino<32, 2>, cudaFuncAttributeMaxDynamicSharedMemorySize, SM9);
    cudaFuncSetAttribute(conv3_wino<16, 1>, cudaFuncAttributeMaxDynamicSharedMemorySize, SM10);

    static cudaStream_t sideQ = nullptr;
    static cudaEvent_t evFork = nullptr, evJoin = nullptr, evC9 = nullptr, evVs = nullptr;
    if (!sideQ) {
        cudaStreamCreateWithFlags(&sideQ, cudaStreamNonBlocking);
        cudaEventCreateWithFlags(&evFork, cudaEventDisableTiming);
        cudaEventCreateWithFlags(&evJoin, cudaEventDisableTiming);
        cudaEventCreateWithFlags(&evC9, cudaEventDisableTiming);
        cudaEventCreateWithFlags(&evVs, cudaEventDisableTiming);
    }

    const int BS = 256;
    const int N = 2;

    // ---- fork: branch A on sideQ ----
    cudaEventRecord(evFork, 0);
    cudaStreamWaitEvent(sideQ, evFork, 0);

    wino_filt<<<gs(64 * 32, BS), BS, 0, sideQ>>>(w9, pool + O_U9, 32);
    wino_filt<<<gs(64 * 16, BS), BS, 0, sideQ>>>(w10, pool + O_U10, 16);
    launch_conv<3, 0, 4, 8>(x, 3, nullptr, 0, pool + O_S1, 3, w_s1, b_s1, 512, 512, N, sideQ);
    maxpool_kernel<<<gs((long)N * 3 * 256 * 256, BS), BS, 0, sideQ>>>(pool + O_S1, pool + O_S2, 3, 256, 256, N);
    maxpool_kernel<<<gs((long)N * 3 * 128 * 128, BS), BS, 0, sideQ>>>(pool + O_S2, pool + O_S3, 3, 128, 128, N);
    maxpool_kernel<<<gs((long)N * 3 * 64 * 64, BS), BS, 0, sideQ>>>(pool + O_S3, pool + O_S4, 3, 64, 64, N);
    for (int n = 0; n < N; ++n)
        cudaMemcpyAsync(pool + O_MULTI + (long)n * 12 * PX, pool + O_S1 + (long)n * 3 * PX,
                        3 * PX * sizeof(float), cudaMemcpyDeviceToDevice, sideQ);
    upsample_kernel<<<gs((long)N * 3 * PX, BS), BS, 0, sideQ>>>(pool + O_S2, pool + O_MULTI + 3 * PX,
        3, 256, 256, 2, 3 * (PX / 4), 12 * PX, N);
    upsample_kernel<<<gs((long)N * 3 * PX, BS), BS, 0, sideQ>>>(pool + O_S3, pool + O_MULTI + 6 * PX,
        3, 128, 128, 4, 3 * (PX / 16), 12 * PX, N);
    upsample_kernel<<<gs((long)N * 3 * PX, BS), BS, 0, sideQ>>>(pool + O_S4, pool + O_MULTI + 9 * PX,
        3, 64, 64, 8, 3 * (PX / 64), 12 * PX, N);
    launch_conv<3, 0, 8, 8>(pool + O_MULTI, 12, nullptr, 0, pool + O_MS, 16, w_mc, b_mc, 512, 512, N, sideQ);
    cudaEventRecord(evJoin, sideQ);

    // ---- branch B: c2 + encoder/decoder (separate maxpool kernels) ----
    launch_conv<5, 1, 8, 4>(x, 3, nullptr, 0, pool + O_C2, 16, w2, b2, 512, 512, N);
    maxpool_kernel<<<gs((long)N * 16 * 256 * 256, BS), BS>>>(pool + O_C2, pool + O_C2P, 16, 256, 256, N);
    launch_conv<3, 1, 8, 8>(pool + O_C2P, 16, nullptr, 0, pool + O_C3, 32, w3, b3, 256, 256, N);
    maxpool_kernel<<<gs((long)N * 32 * 128 * 128, BS), BS>>>(pool + O_C3, pool + O_C3P, 32, 128, 128, N);
    launch_conv<3, 1, 8, 8>(pool + O_C3P, 32, nullptr, 0, pool + O_C4, 32, w4, b4, 128, 128, N);
    maxpool_kernel<<<gs((long)N * 32 * 64 * 64, BS), BS>>>(pool + O_C4, pool + O_C4P, 32, 64, 64, N);
    launch_conv<3, 1, 8, 4>(pool + O_C4P, 32, nullptr, 0, pool + O_C5, 32, w5, b5, 64, 64, N);
    maxpool_kernel<<<gs((long)N * 32 * 32 * 32, BS), BS>>>(pool + O_C5, pool + O_C5P, 32, 32, 32, N);
    launch_conv<3, 1, 8, 4>(pool + O_C5P, 32, nullptr, 0, pool + O_C6, 64, w6, b6, 32, 32, N);
    upsample_kernel<<<gs((long)N * 64 * 64 * 64, BS), BS>>>(pool + O_C6, pool + O_C6U,
        64, 32, 32, 2, 64L * 32 * 32, 64L * 64 * 64, N);
    launch_conv<3, 1, 8, 4>(pool + O_C6U, 64, nullptr, 0, pool + O_C6S, 64, w6s, b6s, 64, 64, N);
    upsample_kernel<<<gs((long)N * 64 * 128 * 128, BS), BS>>>(pool + O_C6S, pool + O_C6RE,
        64, 64, 64, 2, 64L * 64 * 64, 64L * 128 * 128, N);
    launch_conv<3, 1, 8, 8>(pool + O_C6RE, 64, pool + O_C4, 32, pool + O_C7C, 32, w7, b7, 128, 128, N);
    upsample_kernel<<<gs((long)N * 32 * 256 * 256, BS), BS>>>(pool + O_C7C, pool + O_C7,
        32, 128, 128, 2, 32L * 128 * 128, 32L * 256 * 256, N);
    launch_conv<3, 1, 8, 8>(pool + O_C7, 32, pool + O_C3, 32, pool + O_C8C, 16, w8, b8, 256, 256, N);
    upsample_kernel<<<gs((long)N * 16 * 512 * 512, BS), BS>>>(pool + O_C8C, pool + O_C8,
        16, 256, 256, 2, 16L * 256 * 256, 16L * 512 * 512, N);

    // ---- join ----
    cudaStreamWaitEvent(0, evJoin, 0);

    {
        dim3 grid(8, 128, N);
        conv3_wino<32, 2><<<grid, 512, SM9>>>(pool + O_C8, 16, pool + O_C2,
                                              pool + O_U9, b9, pool + O_C9);
    }
    // overlap hscan (default) with vscan34 (sideQ): disjoint outputs
    cudaEventRecord(evC9, 0);
    cudaStreamWaitEvent(sideQ, evC9, 0);
    vscan34_blk<<<512, 256, 0, sideQ>>>();
    cudaEventRecord(evVs, sideQ);
    hscan_fused<<<2048, 256>>>();
    cudaStreamWaitEvent(0, evVs, 0);
    vscan78_blk<<<512, 256>>>();
    {
        dim3 grid(8, 128, N);
        conv3_wino<16, 1><<<grid, 512, SM10>>>(pool + O_ELT, 16, nullptr,
                                               pool + O_U10, b10, pool + O_C10);
    }
    launch_conv<3, 1, 4, 8>(pool + O_C10, 64, nullptr, 0, out, 3, w11, b11, 512, 512, N);
}

// round 15
// speedup vs baseline: 1.1620x; 1.0411x over previous
#include <cuda_runtime.h>
#include <math.h>
#include <stdint.h>

static constexpr long PX = 512L * 512;
static constexpr long O_S1    = 0;
static constexpr long O_S2    = O_S1    + 6 * PX;
static constexpr long O_S3    = O_S2    + 6 * (PX / 4);
static constexpr long O_S4    = O_S3    + 6 * (PX / 16);
static constexpr long O_MULTI = O_S4    + 6 * (PX / 64);
static constexpr long O_MS    = O_MULTI + 24 * PX;
static constexpr long O_C2    = O_MS    + 32 * PX;
static constexpr long O_C2P   = O_C2    + 32 * PX;
static constexpr long O_C3    = O_C2P   + 32 * (PX / 4);
static constexpr long O_C3P   = O_C3    + 64 * (PX / 4);
static constexpr long O_C4    = O_C3P   + 64 * (PX / 16);
static constexpr long O_C4P   = O_C4    + 64 * (PX / 16);
static constexpr long O_C5    = O_C4P   + 64 * (PX / 64);
static constexpr long O_C5P   = O_C5    + 64 * (PX / 64);
static constexpr long O_C6    = O_C5P   + 64 * (PX / 256);
static constexpr long O_C6U   = O_C6    + 128 * (PX / 256);
static constexpr long O_C6S   = O_C6U   + 128 * (PX / 64);
static constexpr long O_C6RE  = O_C6S   + 128 * (PX / 64);
static constexpr long O_C7C   = O_C6RE  + 128 * (PX / 16);
static constexpr long O_C7    = O_C7C   + 64 * (PX / 16);
static constexpr long O_C8C   = O_C7    + 64 * (PX / 4);
static constexpr long O_C8    = O_C8C   + 32 * (PX / 4);
static constexpr long O_C9    = O_C8    + 32 * PX;
static constexpr long O_H3    = O_C9    + 128 * PX;
static constexpr long O_H4    = O_H3    + 32 * PX;
static constexpr long O_HM    = O_H4    + 32 * PX;
static constexpr long O_ELT   = O_HM    + 32 * PX;
static constexpr long O_C10   = O_ELT   + 32 * PX;
static constexpr long O_U9    = O_C10   + 128 * PX;
static constexpr long O_U10   = O_U9    + 32768;
static constexpr long POOL_TOTAL = O_U10 + 16384;

__device__ float g_pool[POOL_TOTAL];

typedef unsigned long long ull;
__device__ __forceinline__ ull pk2(float lo, float hi) {
    ull r; asm("mov.b64 %0, {%1, %2};" : "=l"(r) : "f"(lo), "f"(hi)); return r;
}
__device__ __forceinline__ void upk2(float& lo, float& hi, ull v) {
    asm("mov.b64 {%0, %1}, %2;" : "=f"(lo), "=f"(hi) : "l"(v));
}
__device__ __forceinline__ ull fma2(ull a, ull b, ull c) {
    ull d; asm("fma.rn.f32x2 %0, %1, %2, %3;" : "=l"(d) : "l"(a), "l"(b), "l"(c)); return d;
}

// ---------------- fp32 direct conv (vectorized interior loads) ----------------
template <int K, int ACT, int CO, int XT>
__global__ __launch_bounds__(128)
void conv2d_pk(const float* __restrict__ srcA, int ca,
               const float* __restrict__ srcB, int cb,
               float* __restrict__ dst, int cout,
               const float* __restrict__ w, const float* __restrict__ bias,
               int H, int W, int N, int nblk)
{
    extern __shared__ float w_s[];
    const int ctot = ca + cb;
    const int coG = (cout + CO - 1) / CO;
    int blk = blockIdx.x;
    int pblk = blk % nblk;
    int cog  = (blk / nblk) % coG;
    int n    = blk / (nblk * coG);
    int co0  = cog * CO;
    const int nw = ctot * K * K;
    for (int i = threadIdx.x; i < nw * CO; i += blockDim.x) {
        int e = i / CO, j = i - e * CO, co = co0 + j;
        w_s[i] = (co < cout) ? __ldg(w + (long)co * nw + e) : 0.0f;
    }
    __syncthreads();
    const int WXT = W / XT;
    int pos = pblk * blockDim.x + threadIdx.x;
    if (pos >= H * WXT) return;
    int y = pos / WXT, x0 = (pos % WXT) * XT;
    constexpr int P = K / 2, CP = CO / 2, NV = K + XT - 1;
    ull acc[CP][XT];
#pragma unroll
    for (int cp = 0; cp < CP; ++cp) {
        float b0 = (co0 + 2 * cp < cout) ? __ldg(bias + co0 + 2 * cp) : 0.0f;
        float b1 = (co0 + 2 * cp + 1 < cout) ? __ldg(bias + co0 + 2 * cp + 1) : 0.0f;
        ull bp = pk2(b0, b1);
#pragma unroll
        for (int m = 0; m < XT; ++m) acc[cp][m] = bp;
    }
    bool lok[P], rok[K - 1 - P];
#pragma unroll
    for (int i = 0; i < P; ++i) lok[i] = (x0 - P + i >= 0);
#pragma unroll
    for (int i = 0; i < K - 1 - P; ++i) rok[i] = (x0 + XT + i < W);

    for (int ci = 0; ci < ctot; ++ci) {
        const float* plane = (ci < ca)
            ? srcA + ((long)n * ca + ci) * H * W
            : srcB + ((long)n * cb + (ci - ca)) * H * W;
        const float* ws = w_s + ci * (K * K * CO);
#pragma unroll
        for (int ky = 0; ky < K; ++ky) {
            int yy = y + ky - P;
            if (yy < 0 || yy >= H) continue;
            const float* rp = plane + (long)yy * W + x0;
            float vf[NV];
#pragma unroll
            for (int q = 0; q < XT / 4; ++q) {
                float4 t = *reinterpret_cast<const float4*>(rp + 4 * q);
                vf[P + 4 * q]     = t.x;
                vf[P + 4 * q + 1] = t.y;
                vf[P + 4 * q + 2] = t.z;
                vf[P + 4 * q + 3] = t.w;
            }
#pragma unroll
            for (int i = 0; i < P; ++i)
                vf[i] = lok[i] ? __ldg(rp + i - P) : 0.0f;
#pragma unroll
            for (int i = 0; i < K - 1 - P; ++i)
                vf[P + XT + i] = rok[i] ? __ldg(rp + XT + i) : 0.0f;

            ull pv[NV];
#pragma unroll
            for (int i = 0; i < NV; ++i) pv[i] = pk2(vf[i], vf[i]);
#pragma unroll
            for (int kx = 0; kx < K; ++kx) {
                const float* we = ws + (ky * K + kx) * CO;
#pragma unroll
                for (int cp = 0; cp < CP; ++cp) {
                    ull wv = *reinterpret_cast<const ull*>(we + 2 * cp);
#pragma unroll
                    for (int m = 0; m < XT; ++m)
                        acc[cp][m] = fma2(wv, pv[kx + m], acc[cp][m]);
                }
            }
        }
    }
#pragma unroll
    for (int cp = 0; cp < CP; ++cp) {
        float o0[XT], o1[XT];
#pragma unroll
        for (int m = 0; m < XT; ++m) upk2(o0[m], o1[m], acc[cp][m]);
#pragma unroll
        for (int h = 0; h < 2; ++h) {
            int co = co0 + 2 * cp + h;
            if (co >= cout) break;
            float* ov = h ? o1 : o0;
#pragma unroll
            for (int m = 0; m < XT; ++m) {
                if (ACT == 1) ov[m] = fmaxf(ov[m], 0.f);
                else if (ACT == 2) ov[m] = tanhf(ov[m]);
            }
            long o = (((long)n * cout + co) * H + y) * W + x0;
#pragma unroll
            for (int q = 0; q < XT / 4; ++q)
                *reinterpret_cast<float4*>(dst + o + 4 * q) =
                    make_float4(ov[4 * q], ov[4 * q + 1], ov[4 * q + 2], ov[4 * q + 3]);
        }
    }
}

// ---------------- Winograd filter transform ----------------
__global__ void wino_filt(const float* __restrict__ w, float* __restrict__ Ut, int CIN)
{
    int idx = blockIdx.x * blockDim.x + threadIdx.x;
    if (idx >= 64 * CIN) return;
    int co = idx / CIN, ci = idx % CIN;
    const float* gp = w + (co * CIN + ci) * 9;
    float g[3][3];
#pragma unroll
    for (int i = 0; i < 3; ++i)
#pragma unroll
        for (int j = 0; j < 3; ++j) g[i][j] = __ldg(gp + i * 3 + j);
    float Gg[4][3];
#pragma unroll
    for (int c = 0; c < 3; ++c) {
        Gg[0][c] = g[0][c];
        Gg[1][c] = 0.5f * (g[0][c] + g[1][c] + g[2][c]);
        Gg[2][c] = 0.5f * (g[0][c] - g[1][c] + g[2][c]);
        Gg[3][c] = g[2][c];
    }
#pragma unroll
    for (int u = 0; u < 4; ++u) {
        float U0 = Gg[u][0];
        float U1 = 0.5f * (Gg[u][0] + Gg[u][1] + Gg[u][2]);
        float U2 = 0.5f * (Gg[u][0] - Gg[u][1] + Gg[u][2]);
        float U3 = Gg[u][2];
        Ut[((u * 4 + 0) * CIN + ci) * 64 + co] = U0;
        Ut[((u * 4 + 1) * CIN + ci) * 64 + co] = U1;
        Ut[((u * 4 + 2) * CIN + ci) * 64 + co] = U2;
        Ut[((u * 4 + 3) * CIN + ci) * 64 + co] = U3;
    }
}

// ---------------- Fused Winograd conv ----------------
// UPS=1: srcA channels are a 256x256 tensor consumed through bilinear 2x
// upsample (half-pixel, clamped) during RAW staging.
template <int CIN, int ACT, int UPS>
__global__ __launch_bounds__(512, 1)
void conv3_wino(const float* __restrict__ srcA, int ca,
                const float* __restrict__ srcB,
                const float* __restrict__ Ut,
                const float* __restrict__ bias,
                float* __restrict__ dst)
{
    extern __shared__ float sm[];
    float* RAW = sm;
    float* VS  = sm + CIN * 408;
    float* MS  = VS + CIN * 272;
    float* BS  = MS + 16896;
    const int tid = threadIdx.x;
    const int bx = blockIdx.x, by = blockIdx.y, n = blockIdx.z;
    if (tid < 64) BS[tid] = __ldg(bias + tid);

    for (int i = tid; i < CIN * 396; i += 512) {
        int c = i % 66, rr = (i / 66) % 6, ci = i / 396;
        int px = bx * 64 + c - 1, py = by * 4 + rr - 1;
        float v = 0.0f;
        if (px >= 0 && px < 512 && py >= 0 && py < 512) {
            if (UPS && ci < ca) {
                // bilinear 2x from 256x256 (exact scale-2 half-pixel form)
                int ys = (py - 1) >> 1, xs = (px - 1) >> 1;
                float wy = (py & 1) ? 0.25f : 0.75f;
                float wx = (px & 1) ? 0.25f : 0.75f;
                int y0c = max(ys, 0), y1c = min(ys + 1, 255);
                int x0c = max(xs, 0), x1c = min(xs + 1, 255);
                const float* p = srcA + (long)(n * ca + ci) * 65536;
                float v00 = __ldg(p + y0c * 256 + x0c);
                float v01 = __ldg(p + y0c * 256 + x1c);
                float v10 = __ldg(p + y1c * 256 + x0c);
                float v11 = __ldg(p + y1c * 256 + x1c);
                v = (1.f - wy) * ((1.f - wx) * v00 + wx * v01)
                  +        wy  * ((1.f - wx) * v10 + wx * v11);
            } else {
                const float* p = (ci < ca)
                    ? srcA + ((long)(n * ca + ci) * 512 + py) * 512 + px
                    : srcB + ((long)(n * (CIN - ca) + (ci - ca)) * 512 + py) * 512 + px;
                v = __ldg(p);
            }
        }
        RAW[ci * 408 + rr * 68 + c] = v;
    }
    __syncthreads();

    ull Y[4][4];
#pragma unroll
    for (int k = 0; k < 4; ++k)
#pragma unroll
        for (int q = 0; q < 4; ++q) Y[k][q] = 0ULL;

    const int lane = tid & 31, wp = tid >> 5;
    const int gv = wp >> 2, coh = (wp >> 1) & 1, tlh = wp & 1;
    const int co0 = coh * 32 + (lane >> 3) * 8;
    const int tl0 = tlh * 32 + (lane & 7) * 4;
    const ull ONE2 = pk2(1.f, 1.f), NEG2 = pk2(-1.f, -1.f);
    const int ia_t[4] = {0, 1, 2, 1}, ib_t[4] = {2, 2, 1, 3};
    const float sb_t[4] = {-1.f, 1.f, -1.f, -1.f};
    const float f0_t[4] = {1.f, 1.f, 1.f, 0.f};
    const float f1_t[4] = {0.f, 1.f, -1.f, -1.f};

    auto v_compute = [&](int g) {
        const int ia = ia_t[g], ib = ib_t[g];
        const ull SB = pk2(sb_t[g], sb_t[g]);
        for (int idx = tid; idx < CIN * 64; idx += 512) {
            int tl = idx & 63, ci = idx >> 6;
            int tly = tl >> 5, tlx = tl & 31;
            const float* rb = RAW + ci * 408 + (tly * 2) * 68 + tlx * 2;
            ull e01 = fma2(*(const ull*)(rb + ib * 68), SB, *(const ull*)(rb + ia * 68));
            ull e23 = fma2(*(const ull*)(rb + ib * 68 + 2), SB, *(const ull*)(rb + ia * 68 + 2));
            float e0, e1, e2, e3;
            upk2(e0, e1, e01); upk2(e2, e3, e23);
            float* vb = VS + ci * 68 + tl;
            vb[0]            = e0 - e2;
            vb[CIN * 68]     = e1 + e2;
            vb[2 * CIN * 68] = e2 - e1;
            vb[3 * CIN * 68] = e1 - e3;
        }
    };

    v_compute(0);
    __syncthreads();

    for (int g = 0; g < 4; ++g) {
        {
            ull acc[4][4];
#pragma unroll
            for (int p = 0; p < 4; ++p)
#pragma unroll
                for (int t = 0; t < 4; ++t) acc[p][t] = 0ULL;
            const float* Ub = Ut + ((long)(g * 4 + gv) * CIN) * 64 + co0;
            const float* Vb = VS + gv * CIN * 68 + tl0;
#pragma unroll 4
            for (int ci = 0; ci < CIN; ++ci) {
                const ull* up = (const ull*)(Ub + ci * 64);
                ull u0 = up[0], u1 = up[1], u2 = up[2], u3 = up[3];
                float4 vv = *(const float4*)(Vb + ci * 68);
                ull p0 = pk2(vv.x, vv.x), p1 = pk2(vv.y, vv.y);
                ull p2 = pk2(vv.z, vv.z), p3 = pk2(vv.w, vv.w);
                acc[0][0] = fma2(u0, p0, acc[0][0]); acc[0][1] = fma2(u0, p1, acc[0][1]);
                acc[0][2] = fma2(u0, p2, acc[0][2]); acc[0][3] = fma2(u0, p3, acc[0][3]);
                acc[1][0] = fma2(u1, p0, acc[1][0]); acc[1][1] = fma2(u1, p1, acc[1][1]);
                acc[1][2] = fma2(u1, p2, acc[1][2]); acc[1][3] = fma2(u1, p3, acc[1][3]);
                acc[2][0] = fma2(u2, p0, acc[2][0]); acc[2][1] = fma2(u2, p1, acc[2][1]);
                acc[2][2] = fma2(u2, p2, acc[2][2]); acc[2][3] = fma2(u2, p3, acc[2][3]);
                acc[3][0] = fma2(u3, p0, acc[3][0]); acc[3][1] = fma2(u3, p1, acc[3][1]);
                acc[3][2] = fma2(u3, p2, acc[3][2]); acc[3][3] = fma2(u3, p3, acc[3][3]);
            }
#pragma unroll
            for (int t = 0; t < 4; ++t)
#pragma unroll
                for (int p = 0; p < 4; ++p)
                    *(ull*)(MS + (gv * 64 + tl0 + t) * 66 + co0 + 2 * p) = acc[p][t];
        }
        __syncthreads();
        {
            const ull F0 = pk2(f0_t[g], f0_t[g]);
            const ull F1 = pk2(f1_t[g], f1_t[g]);
            int tl = tid & 63, cpg = tid >> 6;
#pragma unroll
            for (int k = 0; k < 4; ++k) {
                int cp = cpg * 4 + k;
                const float* mb = MS + tl * 66 + 2 * cp;
                ull m0 = *(const ull*)(mb);
                ull m1 = *(const ull*)(mb + 4224);
                ull m2 = *(const ull*)(mb + 8448);
                ull m3 = *(const ull*)(mb + 12672);
                ull z0 = fma2(m2, ONE2, fma2(m1, ONE2, m0));
                ull z1 = fma2(m3, NEG2, fma2(m2, NEG2, m1));
                Y[k][0] = fma2(z0, F0, Y[k][0]);
                Y[k][1] = fma2(z1, F0, Y[k][1]);
                Y[k][2] = fma2(z0, F1, Y[k][2]);
                Y[k][3] = fma2(z1, F1, Y[k][3]);
            }
        }
        if (g < 3) v_compute(g + 1);
        __syncthreads();
    }
    {
        int tl = tid & 63, cpg = tid >> 6;
        int tly = tl >> 5, tlx = tl & 31;
#pragma unroll
        for (int k = 0; k < 4; ++k) {
            int cp = cpg * 4 + k;
            float b0 = BS[2 * cp], b1 = BS[2 * cp + 1];
#pragma unroll
            for (int i = 0; i < 2; ++i)
#pragma unroll
                for (int j = 0; j < 2; ++j) {
                    float v0, v1;
                    upk2(v0, v1, Y[k][i * 2 + j]);
                    v0 += b0; v1 += b1;
                    if (ACT == 1) { v0 = fmaxf(v0, 0.f); v1 = fmaxf(v1, 0.f); }
                    else          { v0 = tanhf(v0);      v1 = tanhf(v1); }
                    int py = by * 4 + tly * 2 + i;
                    int px = bx * 64 + tlx * 2 + j;
                    dst[((long)(n * 64 + 2 * cp) * 512 + py) * 512 + px]     = v0;
                    dst[((long)(n * 64 + 2 * cp + 1) * 512 + py) * 512 + px] = v1;
                }
        }
    }
}

// ---------------- pool / upsample ----------------
__global__ void maxpool_kernel(const float* __restrict__ src, float* __restrict__ dst,
                               int C, int Ho, int Wo, int N)
{
    long idx = (long)blockIdx.x * blockDim.x + threadIdx.x;
    long total = (long)N * C * Ho * Wo;
    if (idx >= total) return;
    int x = (int)(idx % Wo);  long t = idx / Wo;
    int y = (int)(t % Ho);    t /= Ho;
    int c = (int)(t % C);
    int n = (int)(t / C);
    int Hi = Ho * 2, Wi = Wo * 2;
    const float* p = src + (((long)n * C + c) * Hi + 2 * y) * Wi + 2 * x;
    dst[idx] = fmaxf(fmaxf(p[0], p[1]), fmaxf(p[Wi], p[Wi + 1]));
}

__global__ void upsample_kernel(const float* __restrict__ src, float* __restrict__ dst,
                                int C, int Hs, int Ws, int scale,
                                long sBS, long dBS, int N)
{
    int Hd = Hs * scale, Wd = Ws * scale;
    long idx = (long)blockIdx.x * blockDim.x + threadIdx.x;
    long total = (long)N * C * Hd * Wd;
    if (idx >= total) return;
    int x = (int)(idx % Wd);  long t = idx / Wd;
    int y = (int)(t % Hd);    t /= Hd;
    int c = (int)(t % C);
    int n = (int)(t / C);
    float inv = 1.0f / (float)scale;
    float fy = (y + 0.5f) * inv - 0.5f;
    float fx = (x + 0.5f) * inv - 0.5f;
    int y0 = (int)floorf(fy), x0 = (int)floorf(fx);
    float wy = fy - (float)y0, wx = fx - (float)x0;
    int y0c = min(max(y0, 0), Hs - 1), y1c = min(max(y0 + 1, 0), Hs - 1);
    int x0c = min(max(x0, 0), Ws - 1), x1c = min(max(x0 + 1, 0), Ws - 1);
    const float* p = src + n * sBS + (long)c * Hs * Ws;
    float v00 = p[(long)y0c * Ws + x0c], v01 = p[(long)y0c * Ws + x1c];
    float v10 = p[(long)y1c * Ws + x0c], v11 = p[(long)y1c * Ws + x1c];
    float v = (1.f - wy) * ((1.f - wx) * v00 + wx * v01)
            +        wy  * ((1.f - wx) * v10 + wx * v11);
    dst[n * dBS + ((long)c * Hd + y) * Wd + x] = v;
}

// ---------------- scans ----------------
__device__ __forceinline__ float warp_affine_prefix(float& A, float& B, int lane)
{
#pragma unroll
    for (int d = 1; d < 32; d <<= 1) {
        float Ap = __shfl_up_sync(0xffffffffu, A, d);
        float Bp = __shfl_up_sync(0xffffffffu, B, d);
        if (lane >= d) { B = fmaf(A, Bp, B); A *= Ap; }
    }
    float yin = __shfl_up_sync(0xffffffffu, B, 1);
    return (lane == 0) ? 0.0f : yin;
}

__global__ __launch_bounds__(256) void hscan_fused()
{
    int gw = (blockIdx.x * blockDim.x + threadIdx.x) >> 5;
    int lane = threadIdx.x & 31;
    int y = gw % 512;  int t = gw / 512;
    int c = t % 16;    int n = t / 16;
    long rowc = ((long)(n * 16 + c) * 512 + y) * 512;
    const float* a1 = g_pool + O_C9 + ((long)(n * 64 + c)      * 512 + y) * 512;
    const float* a2 = g_pool + O_C9 + ((long)(n * 64 + 32 + c) * 512 + y) * 512;
    const float* u  = g_pool + O_MS + rowc;
    float* hm = g_pool + O_HM + rowc;
    int x0 = lane * 16, mlane = 31 - lane;

    float a1v[16], ufv[16], h1v[16], h2v[16];
#pragma unroll
    for (int k = 0; k < 16; ++k) { a1v[k] = a1[x0 + k]; ufv[k] = u[x0 + k]; }
    float A = 1.f, B = 0.f;
#pragma unroll
    for (int k = 0; k < 16; ++k) {
        float av = a1v[k];
        B = fmaf(av, B, (1.f - av) * ufv[k]);
        A *= av;
    }
    float yv = warp_affine_prefix(A, B, lane);
#pragma unroll
    for (int k = 0; k < 16; ++k) {
        float av = a1v[k];
        yv = fmaf(av, yv, (1.f - av) * ufv[k]);
        h1v[k] = yv;
    }
    float u2v[16];
#pragma unroll
    for (int k = 0; k < 16; ++k)
        u2v[k] = __shfl_sync(0xffffffffu, ufv[15 - k], mlane);
    A = 1.f; B = 0.f;
#pragma unroll
    for (int k = 0; k < 16; ++k) {
        float av = a1v[k];
        B = fmaf(av, B, (1.f - av) * u2v[k]);
        A *= av;
    }
    yv = warp_affine_prefix(A, B, lane);
#pragma unroll
    for (int k = 0; k < 16; ++k) {
        float av = a1v[k];
        yv = fmaf(av, yv, (1.f - av) * u2v[k]);
        h2v[k] = yv;
    }
#pragma unroll
    for (int k = 0; k < 16; ++k) a1v[k] = a2[x0 + k];
    A = 1.f; B = 0.f;
#pragma unroll
    for (int k = 0; k < 16; ++k) {
        float av = a1v[k];
        B = fmaf(av, B, (1.f - av) * h1v[k]);
        A *= av;
    }
    yv = warp_affine_prefix(A, B, lane);
#pragma unroll
    for (int k = 0; k < 16; ++k) {
        float av = a1v[k];
        yv = fmaf(av, yv, (1.f - av) * h1v[k]);
        h1v[k] = yv;
    }
    float u6v[16];
#pragma unroll
    for (int k = 0; k < 16; ++k)
        u6v[k] = __shfl_sync(0xffffffffu, h2v[15 - k], mlane);
    A = 1.f; B = 0.f;
#pragma unroll
    for (int k = 0; k < 16; ++k) {
        float av = a1v[k];
        B = fmaf(av, B, (1.f - av) * u6v[k]);
        A *= av;
    }
    yv = warp_affine_prefix(A, B, lane);
#pragma unroll
    for (int k = 0; k < 16; ++k) {
        float av = a1v[k];
        yv = fmaf(av, yv, (1.f - av) * u6v[k]);
        hm[x0 + k] = fmaxf(h1v[k], yv);
    }
}

__global__ __launch_bounds__(256) void vscan34_blk()
{
    int blk = blockIdx.x;
    int strip = blk & 15;  int t = blk >> 4;
    int c = t & 15;        int n = t >> 4;
    int lx = threadIdx.x & 31, g = threadIdx.x >> 5;
    int x = strip * 32 + lx;
    const float* gx1 = g_pool + O_C9 + (long)(n * 64 + c)      * PX;
    const float* gy1 = g_pool + O_C9 + (long)(n * 64 + 16 + c) * PX;
    const float* u   = g_pool + O_MS + (long)(n * 16 + c) * PX;
    float* h3 = g_pool + O_H3 + (long)(n * 16 + c) * PX;
    float* h4 = g_pool + O_H4 + (long)(n * 16 + c) * PX;
    __shared__ float sA[8][33], s3[8][33], s4[8][33];
    int y0 = g << 6;
    float A = 1.f, B3 = 0.f, B4 = 0.f;
    for (int i = 0; i < 64; ++i) {
        int y = y0 + i;
        float av = (y == 0) ? gy1[x] : gx1[(long)y * 512 + x];
        float om = 1.f - av;
        B3 = fmaf(av, B3, om * u[(long)y * 512 + x]);
        B4 = fmaf(av, B4, om * u[(long)(511 - y) * 512 + x]);
        A *= av;
    }
    sA[g][lx] = A; s3[g][lx] = B3; s4[g][lx] = B4;
    __syncthreads();
    if (g == 0) {
        float p3 = 0.f, p4 = 0.f;
        for (int gg = 0; gg < 8; ++gg) {
            float a_ = sA[gg][lx], b3 = s3[gg][lx], b4 = s4[gg][lx];
            s3[gg][lx] = p3; s4[gg][lx] = p4;
            p3 = fmaf(a_, p3, b3); p4 = fmaf(a_, p4, b4);
        }
    }
    __syncthreads();
    float y3 = s3[g][lx], y4 = s4[g][lx];
    for (int i = 0; i < 64; ++i) {
        int y = y0 + i;
        float av = (y == 0) ? gy1[x] : gx1[(long)y * 512 + x];
        float om = 1.f - av;
        y3 = fmaf(av, y3, om * u[(long)y * 512 + x]);
        h3[(long)y * 512 + x] = y3;
        y4 = fmaf(av, y4, om * u[(long)(511 - y) * 512 + x]);
        h4[(long)y * 512 + x] = y4;
    }
}

__global__ __launch_bounds__(256) void vscan78_blk()
{
    int blk = blockIdx.x;
    int strip = blk & 15;  int t = blk >> 4;
    int c = t & 15;        int n = t >> 4;
    int lx = threadIdx.x & 31, g = threadIdx.x >> 5;
    int x = strip * 32 + lx;
    const float* a  = g_pool + O_C9 + (long)(n * 64 + 48 + c) * PX;
    const float* h3 = g_pool + O_H3 + (long)(n * 16 + c) * PX;
    const float* h4 = g_pool + O_H4 + (long)(n * 16 + c) * PX;
    const float* hm = g_pool + O_HM + (long)(n * 16 + c) * PX;
    float* elt = g_pool + O_ELT + (long)(n * 16 + c) * PX;
    __shared__ float sA[8][33], s7[8][33], s8[8][33];
    int y0 = g << 6;
    float A = 1.f, B7 = 0.f, B8 = 0.f;
    for (int i = 0; i < 64; ++i) {
        int y = y0 + i;
        float av = a[(long)y * 512 + x];
        float om = 1.f - av;
        B7 = fmaf(av, B7, om * h3[(long)y * 512 + x]);
        B8 = fmaf(av, B8, om * h4[(long)(511 - y) * 512 + x]);
        A *= av;
    }
    sA[g][lx] = A; s7[g][lx] = B7; s8[g][lx] = B8;
    __syncthreads();
    if (g == 0) {
        float p7 = 0.f, p8 = 0.f;
        for (int gg = 0; gg < 8; ++gg) {
            float a_ = sA[gg][lx], b7 = s7[gg][lx], b8 = s8[gg][lx];
            s7[gg][lx] = p7; s8[gg][lx] = p8;
            p7 = fmaf(a_, p7, b7); p8 = fmaf(a_, p8, b8);
        }
    }
    __syncthreads();
    float y7 = s7[g][lx], y8 = s8[g][lx];
    for (int i = 0; i < 64; ++i) {
        int y = y0 + i;
        float av = a[(long)y * 512 + x];
        float om = 1.f - av;
        y7 = fmaf(av, y7, om * h3[(long)y * 512 + x]);
        y8 = fmaf(av, y8, om * h4[(long)(511 - y) * 512 + x]);
        elt[(long)y * 512 + x] = fmaxf(hm[(long)y * 512 + x], fmaxf(y7, y8));
    }
}

// ---------------- launch ----------------
static inline int gs(long total, int bs) { return (int)((total + bs - 1) / bs); }

template <int K, int ACT, int CO, int XT>
static void launch_conv(const float* srcA, int ca, const float* srcB, int cb,
                        float* dst, int cout, const float* w, const float* b,
                        int H, int W, int N, cudaStream_t st = 0)
{
    const int BT = 128;
    int WXT = W / XT;
    int nblk = (H * WXT + BT - 1) / BT;
    int coG = (cout + CO - 1) / CO;
    int blocks = N * coG * nblk;
    int smem = (ca + cb) * K * K * CO * (int)sizeof(float);
    conv2d_pk<K, ACT, CO, XT><<<blocks, BT, smem, st>>>(srcA, ca, srcB, cb, dst, cout, w, b, H, W, N, nblk);
}

extern "C" void kernel_launch(void* const* d_in, const int* in_sizes, int n_in,
                              void* d_out, int out_size)
{
    const float* x    = (const float*)d_in[0];
    const float* w_s1 = (const float*)d_in[1];  const float* b_s1 = (const float*)d_in[2];
    const float* w_mc = (const float*)d_in[3];  const float* b_mc = (const float*)d_in[4];
    const float* w2   = (const float*)d_in[5];  const float* b2   = (const float*)d_in[6];
    const float* w3   = (const float*)d_in[7];  const float* b3   = (const float*)d_in[8];
    const float* w4   = (const float*)d_in[9];  const float* b4   = (const float*)d_in[10];
    const float* w5   = (const float*)d_in[11]; const float* b5   = (const float*)d_in[12];
    const float* w6   = (const float*)d_in[13]; const float* b6   = (const float*)d_in[14];
    const float* w6s  = (const float*)d_in[15]; const float* b6s  = (const float*)d_in[16];
    const float* w7   = (const float*)d_in[17]; const float* b7   = (const float*)d_in[18];
    const float* w8   = (const float*)d_in[19]; const float* b8   = (const float*)d_in[20];
    const float* w9   = (const float*)d_in[21]; const float* b9   = (const float*)d_in[22];
    const float* w10  = (const float*)d_in[23]; const float* b10  = (const float*)d_in[24];
    const float* w11  = (const float*)d_in[25]; const float* b11  = (const float*)d_in[26];
    float* out = (float*)d_out;

    float* pool = nullptr;
    cudaGetSymbolAddress((void**)&pool, g_pool);

    static const int SM9  = (32 * 408 + 32 * 272 + 16896 + 64) * 4;
    static const int SM10 = (16 * 408 + 16 * 272 + 16896 + 64) * 4;
    cudaFuncSetAttribute(conv3_wino<32, 2, 1>, cudaFuncAttributeMaxDynamicSharedMemorySize, SM9);
    cudaFuncSetAttribute(conv3_wino<16, 1, 0>, cudaFuncAttributeMaxDynamicSharedMemorySize, SM10);

    static cudaStream_t sideQ = nullptr;
    static cudaEvent_t evFork = nullptr, evJoin = nullptr;
    if (!sideQ) {
        cudaStreamCreateWithFlags(&sideQ, cudaStreamNonBlocking);
        cudaEventCreateWithFlags(&evFork, cudaEventDisableTiming);
        cudaEventCreateWithFlags(&evJoin, cudaEventDisableTiming);
    }

    const int BS = 256;
    const int N = 2;

    // ---- fork: branch A on sideQ ----
    cudaEventRecord(evFork, 0);
    cudaStreamWaitEvent(sideQ, evFork, 0);

    wino_filt<<<gs(64 * 32, BS), BS, 0, sideQ>>>(w9, pool + O_U9, 32);
    wino_filt<<<gs(64 * 16, BS), BS, 0, sideQ>>>(w10, pool + O_U10, 16);
    launch_conv<3, 0, 4, 8>(x, 3, nullptr, 0, pool + O_S1, 3, w_s1, b_s1, 512, 512, N, sideQ);
    maxpool_kernel<<<gs((long)N * 3 * 256 * 256, BS), BS, 0, sideQ>>>(pool + O_S1, pool + O_S2, 3, 256, 256, N);
    maxpool_kernel<<<gs((long)N * 3 * 128 * 128, BS), BS, 0, sideQ>>>(pool + O_S2, pool + O_S3, 3, 128, 128, N);
    maxpool_kernel<<<gs((long)N * 3 * 64 * 64, BS), BS, 0, sideQ>>>(pool + O_S3, pool + O_S4, 3, 64, 64, N);
    for (int n = 0; n < N; ++n)
        cudaMemcpyAsync(pool + O_MULTI + (long)n * 12 * PX, pool + O_S1 + (long)n * 3 * PX,
                        3 * PX * sizeof(float), cudaMemcpyDeviceToDevice, sideQ);
    upsample_kernel<<<gs((long)N * 3 * PX, BS), BS, 0, sideQ>>>(pool + O_S2, pool + O_MULTI + 3 * PX,
        3, 256, 256, 2, 3 * (PX / 4), 12 * PX, N);
    upsample_kernel<<<gs((long)N * 3 * PX, BS), BS, 0, sideQ>>>(pool + O_S3, pool + O_MULTI + 6 * PX,
        3, 128, 128, 4, 3 * (PX / 16), 12 * PX, N);
    upsample_kernel<<<gs((long)N * 3 * PX, BS), BS, 0, sideQ>>>(pool + O_S4, pool + O_MULTI + 9 * PX,
        3, 64, 64, 8, 3 * (PX / 64), 12 * PX, N);
    launch_conv<3, 0, 8, 8>(pool + O_MULTI, 12, nullptr, 0, pool + O_MS, 16, w_mc, b_mc, 512, 512, N, sideQ);
    cudaEventRecord(evJoin, sideQ);

    // ---- branch B: c2 + encoder/decoder ----
    launch_conv<5, 1, 8, 4>(x, 3, nullptr, 0, pool + O_C2, 16, w2, b2, 512, 512, N);
    maxpool_kernel<<<gs((long)N * 16 * 256 * 256, BS), BS>>>(pool + O_C2, pool + O_C2P, 16, 256, 256, N);
    launch_conv<3, 1, 8, 8>(pool + O_C2P, 16, nullptr, 0, pool + O_C3, 32, w3, b3, 256, 256, N);
    maxpool_kernel<<<gs((long)N * 32 * 128 * 128, BS), BS>>>(pool + O_C3, pool + O_C3P, 32, 128, 128, N);
    launch_conv<3, 1, 8, 8>(pool + O_C3P, 32, nullptr, 0, pool + O_C4, 32, w4, b4, 128, 128, N);
    maxpool_kernel<<<gs((long)N * 32 * 64 * 64, BS), BS>>>(pool + O_C4, pool + O_C4P, 32, 64, 64, N);
    launch_conv<3, 1, 8, 4>(pool + O_C4P, 32, nullptr, 0, pool + O_C5, 32, w5, b5, 64, 64, N);
    maxpool_kernel<<<gs((long)N * 32 * 32 * 32, BS), BS>>>(pool + O_C5, pool + O_C5P, 32, 32, 32, N);
    launch_conv<3, 1, 8, 4>(pool + O_C5P, 32, nullptr, 0, pool + O_C6, 64, w6, b6, 32, 32, N);
    upsample_kernel<<<gs((long)N * 64 * 64 * 64, BS), BS>>>(pool + O_C6, pool + O_C6U,
        64, 32, 32, 2, 64L * 32 * 32, 64L * 64 * 64, N);
    launch_conv<3, 1, 8, 4>(pool + O_C6U, 64, nullptr, 0, pool + O_C6S, 64, w6s, b6s, 64, 64, N);
    upsample_kernel<<<gs((long)N * 64 * 128 * 128, BS), BS>>>(pool + O_C6S, pool + O_C6RE,
        64, 64, 64, 2, 64L * 64 * 64, 64L * 128 * 128, N);
    launch_conv<3, 1, 8, 8>(pool + O_C6RE, 64, pool + O_C4, 32, pool + O_C7C, 32, w7, b7, 128, 128, N);
    upsample_kernel<<<gs((long)N * 32 * 256 * 256, BS), BS>>>(pool + O_C7C, pool + O_C7,
        32, 128, 128, 2, 32L * 128 * 128, 32L * 256 * 256, N);
    launch_conv<3, 1, 8, 8>(pool + O_C7, 32, pool + O_C3, 32, pool + O_C8C, 16, w8, b8, 256, 256, N);
    // c8 upsample is fused into conv3_wino<32,2,1> below

    // ---- join ----
    cudaStreamWaitEvent(0, evJoin, 0);

    {
        dim3 grid(8, 128, N);
        conv3_wino<32, 2, 1><<<grid, 512, SM9>>>(pool + O_C8C, 16, pool + O_C2,
                                                 pool + O_U9, b9, pool + O_C9);
    }
    hscan_fused<<<2048, 256>>>();
    vscan34_blk<<<512, 256>>>();
    vscan78_blk<<<512, 256>>>();
    {
        dim3 grid(8, 128, N);
        conv3_wino<16, 1, 0><<<grid, 512, SM10>>>(pool + O_ELT, 16, nullptr,
                                                  pool + O_U10, b10, pool + O_C10);
    }
    launch_conv<3, 1, 4, 8>(pool + O_C10, 64, nullptr, 0, out, 3, w11, b11, 512, 512, N);
}

// round 16
// speedup vs baseline: 1.1655x; 1.0030x over previous
#include <cuda_runtime.h>
#include <math.h>
#include <stdint.h>

static constexpr long PX = 512L * 512;
static constexpr long O_S1    = 0;
static constexpr long O_S2    = O_S1    + 6 * PX;
static constexpr long O_S3    = O_S2    + 6 * (PX / 4);
static constexpr long O_S4    = O_S3    + 6 * (PX / 16);
static constexpr long O_MULTI = O_S4    + 6 * (PX / 64);
static constexpr long O_MS    = O_MULTI + 24 * PX;
static constexpr long O_C2    = O_MS    + 32 * PX;
static constexpr long O_C2P   = O_C2    + 32 * PX;
static constexpr long O_C3    = O_C2P   + 32 * (PX / 4);
static constexpr long O_C3P   = O_C3    + 64 * (PX / 4);
static constexpr long O_C4    = O_C3P   + 64 * (PX / 16);
static constexpr long O_C4P   = O_C4    + 64 * (PX / 16);
static constexpr long O_C5    = O_C4P   + 64 * (PX / 64);
static constexpr long O_C5P   = O_C5    + 64 * (PX / 64);
static constexpr long O_C6    = O_C5P   + 64 * (PX / 256);
static constexpr long O_C6U   = O_C6    + 128 * (PX / 256);
static constexpr long O_C6S   = O_C6U   + 128 * (PX / 64);
static constexpr long O_C6RE  = O_C6S   + 128 * (PX / 64);
static constexpr long O_C7C   = O_C6RE  + 128 * (PX / 16);
static constexpr long O_C7    = O_C7C   + 64 * (PX / 16);
static constexpr long O_C8C   = O_C7    + 64 * (PX / 4);
static constexpr long O_C8    = O_C8C   + 32 * (PX / 4);
static constexpr long O_C9    = O_C8    + 32 * PX;
static constexpr long O_H3    = O_C9    + 128 * PX;
static constexpr long O_H4    = O_H3    + 32 * PX;
static constexpr long O_HM    = O_H4    + 32 * PX;
static constexpr long O_ELT   = O_HM    + 32 * PX;
static constexpr long O_C10   = O_ELT   + 32 * PX;
static constexpr long O_U9    = O_C10   + 128 * PX;
static constexpr long O_U10   = O_U9    + 32768;
static constexpr long POOL_TOTAL = O_U10 + 16384;

__device__ float g_pool[POOL_TOTAL];

typedef unsigned long long ull;
__device__ __forceinline__ ull pk2(float lo, float hi) {
    ull r; asm("mov.b64 %0, {%1, %2};" : "=l"(r) : "f"(lo), "f"(hi)); return r;
}
__device__ __forceinline__ void upk2(float& lo, float& hi, ull v) {
    asm("mov.b64 {%0, %1}, %2;" : "=f"(lo), "=f"(hi) : "l"(v));
}
__device__ __forceinline__ ull fma2(ull a, ull b, ull c) {
    ull d; asm("fma.rn.f32x2 %0, %1, %2, %3;" : "=l"(d) : "l"(a), "l"(b), "l"(c)); return d;
}

// ---------------- fp32 direct conv (vectorized interior loads) ----------------
template <int K, int ACT, int CO, int XT>
__global__ __launch_bounds__(128)
void conv2d_pk(const float* __restrict__ srcA, int ca,
               const float* __restrict__ srcB, int cb,
               float* __restrict__ dst, int cout,
               const float* __restrict__ w, const float* __restrict__ bias,
               int H, int W, int N, int nblk)
{
    extern __shared__ float w_s[];
    const int ctot = ca + cb;
    const int coG = (cout + CO - 1) / CO;
    int blk = blockIdx.x;
    int pblk = blk % nblk;
    int cog  = (blk / nblk) % coG;
    int n    = blk / (nblk * coG);
    int co0  = cog * CO;
    const int nw = ctot * K * K;
    for (int i = threadIdx.x; i < nw * CO; i += blockDim.x) {
        int e = i / CO, j = i - e * CO, co = co0 + j;
        w_s[i] = (co < cout) ? __ldg(w + (long)co * nw + e) : 0.0f;
    }
    __syncthreads();
    const int WXT = W / XT;
    int pos = pblk * blockDim.x + threadIdx.x;
    if (pos >= H * WXT) return;
    int y = pos / WXT, x0 = (pos % WXT) * XT;
    constexpr int P = K / 2, CP = CO / 2, NV = K + XT - 1;
    ull acc[CP][XT];
#pragma unroll
    for (int cp = 0; cp < CP; ++cp) {
        float b0 = (co0 + 2 * cp < cout) ? __ldg(bias + co0 + 2 * cp) : 0.0f;
        float b1 = (co0 + 2 * cp + 1 < cout) ? __ldg(bias + co0 + 2 * cp + 1) : 0.0f;
        ull bp = pk2(b0, b1);
#pragma unroll
        for (int m = 0; m < XT; ++m) acc[cp][m] = bp;
    }
    bool lok[P], rok[K - 1 - P];
#pragma unroll
    for (int i = 0; i < P; ++i) lok[i] = (x0 - P + i >= 0);
#pragma unroll
    for (int i = 0; i < K - 1 - P; ++i) rok[i] = (x0 + XT + i < W);

    for (int ci = 0; ci < ctot; ++ci) {
        const float* plane = (ci < ca)
            ? srcA + ((long)n * ca + ci) * H * W
            : srcB + ((long)n * cb + (ci - ca)) * H * W;
        const float* ws = w_s + ci * (K * K * CO);
#pragma unroll
        for (int ky = 0; ky < K; ++ky) {
            int yy = y + ky - P;
            if (yy < 0 || yy >= H) continue;
            const float* rp = plane + (long)yy * W + x0;
            float vf[NV];
#pragma unroll
            for (int q = 0; q < XT / 4; ++q) {
                float4 t = *reinterpret_cast<const float4*>(rp + 4 * q);
                vf[P + 4 * q]     = t.x;
                vf[P + 4 * q + 1] = t.y;
                vf[P + 4 * q + 2] = t.z;
                vf[P + 4 * q + 3] = t.w;
            }
#pragma unroll
            for (int i = 0; i < P; ++i)
                vf[i] = lok[i] ? __ldg(rp + i - P) : 0.0f;
#pragma unroll
            for (int i = 0; i < K - 1 - P; ++i)
                vf[P + XT + i] = rok[i] ? __ldg(rp + XT + i) : 0.0f;

            ull pv[NV];
#pragma unroll
            for (int i = 0; i < NV; ++i) pv[i] = pk2(vf[i], vf[i]);
#pragma unroll
            for (int kx = 0; kx < K; ++kx) {
                const float* we = ws + (ky * K + kx) * CO;
#pragma unroll
                for (int cp = 0; cp < CP; ++cp) {
                    ull wv = *reinterpret_cast<const ull*>(we + 2 * cp);
#pragma unroll
                    for (int m = 0; m < XT; ++m)
                        acc[cp][m] = fma2(wv, pv[kx + m], acc[cp][m]);
                }
            }
        }
    }
#pragma unroll
    for (int cp = 0; cp < CP; ++cp) {
        float o0[XT], o1[XT];
#pragma unroll
        for (int m = 0; m < XT; ++m) upk2(o0[m], o1[m], acc[cp][m]);
#pragma unroll
        for (int h = 0; h < 2; ++h) {
            int co = co0 + 2 * cp + h;
            if (co >= cout) break;
            float* ov = h ? o1 : o0;
#pragma unroll
            for (int m = 0; m < XT; ++m) {
                if (ACT == 1) ov[m] = fmaxf(ov[m], 0.f);
                else if (ACT == 2) ov[m] = tanhf(ov[m]);
            }
            long o = (((long)n * cout + co) * H + y) * W + x0;
#pragma unroll
            for (int q = 0; q < XT / 4; ++q)
                *reinterpret_cast<float4*>(dst + o + 4 * q) =
                    make_float4(ov[4 * q], ov[4 * q + 1], ov[4 * q + 2], ov[4 * q + 3]);
        }
    }
}

// ---------------- Winograd filter transform ----------------
__global__ void wino_filt(const float* __restrict__ w, float* __restrict__ Ut, int CIN)
{
    int idx = blockIdx.x * blockDim.x + threadIdx.x;
    if (idx >= 64 * CIN) return;
    int co = idx / CIN, ci = idx % CIN;
    const float* gp = w + (co * CIN + ci) * 9;
    float g[3][3];
#pragma unroll
    for (int i = 0; i < 3; ++i)
#pragma unroll
        for (int j = 0; j < 3; ++j) g[i][j] = __ldg(gp + i * 3 + j);
    float Gg[4][3];
#pragma unroll
    for (int c = 0; c < 3; ++c) {
        Gg[0][c] = g[0][c];
        Gg[1][c] = 0.5f * (g[0][c] + g[1][c] + g[2][c]);
        Gg[2][c] = 0.5f * (g[0][c] - g[1][c] + g[2][c]);
        Gg[3][c] = g[2][c];
    }
#pragma unroll
    for (int u = 0; u < 4; ++u) {
        float U0 = Gg[u][0];
        float U1 = 0.5f * (Gg[u][0] + Gg[u][1] + Gg[u][2]);
        float U2 = 0.5f * (Gg[u][0] - Gg[u][1] + Gg[u][2]);
        float U3 = Gg[u][2];
        Ut[((u * 4 + 0) * CIN + ci) * 64 + co] = U0;
        Ut[((u * 4 + 1) * CIN + ci) * 64 + co] = U1;
        Ut[((u * 4 + 2) * CIN + ci) * 64 + co] = U2;
        Ut[((u * 4 + 3) * CIN + ci) * 64 + co] = U3;
    }
}

// ---------------- Fused Winograd conv ----------------
// UPS=1: srcA consumed through bilinear 2x upsample during RAW staging.
// PRUNE=1: skip Y-combine/epilogue for cout 16..31 when by>0 (dead gy1 rows).
template <int CIN, int ACT, int UPS, int PRUNE>
__global__ __launch_bounds__(512, 1)
void conv3_wino(const float* __restrict__ srcA, int ca,
                const float* __restrict__ srcB,
                const float* __restrict__ Ut,
                const float* __restrict__ bias,
                float* __restrict__ dst)
{
    extern __shared__ float sm[];
    float* RAW = sm;
    float* VS  = sm + CIN * 408;
    float* MS  = VS + CIN * 272;
    float* BS  = MS + 16896;
    const int tid = threadIdx.x;
    const int bx = blockIdx.x, by = blockIdx.y, n = blockIdx.z;
    if (tid < 64) BS[tid] = __ldg(bias + tid);

    for (int i = tid; i < CIN * 396; i += 512) {
        int c = i % 66, rr = (i / 66) % 6, ci = i / 396;
        int px = bx * 64 + c - 1, py = by * 4 + rr - 1;
        float v = 0.0f;
        if (px >= 0 && px < 512 && py >= 0 && py < 512) {
            if (UPS && ci < ca) {
                int ys = (py - 1) >> 1, xs = (px - 1) >> 1;
                float wy = (py & 1) ? 0.25f : 0.75f;
                float wx = (px & 1) ? 0.25f : 0.75f;
                int y0c = max(ys, 0), y1c = min(ys + 1, 255);
                int x0c = max(xs, 0), x1c = min(xs + 1, 255);
                const float* p = srcA + (long)(n * ca + ci) * 65536;
                float v00 = __ldg(p + y0c * 256 + x0c);
                float v01 = __ldg(p + y0c * 256 + x1c);
                float v10 = __ldg(p + y1c * 256 + x0c);
                float v11 = __ldg(p + y1c * 256 + x1c);
                v = (1.f - wy) * ((1.f - wx) * v00 + wx * v01)
                  +        wy  * ((1.f - wx) * v10 + wx * v11);
            } else {
                const float* p = (ci < ca)
                    ? srcA + ((long)(n * ca + ci) * 512 + py) * 512 + px
                    : srcB + ((long)(n * (CIN - ca) + (ci - ca)) * 512 + py) * 512 + px;
                v = __ldg(p);
            }
        }
        RAW[ci * 408 + rr * 68 + c] = v;
    }
    __syncthreads();

    ull Y[4][4];
#pragma unroll
    for (int k = 0; k < 4; ++k)
#pragma unroll
        for (int q = 0; q < 4; ++q) Y[k][q] = 0ULL;

    const int lane = tid & 31, wp = tid >> 5;
    const int gv = wp >> 2, coh = (wp >> 1) & 1, tlh = wp & 1;
    const int co0 = coh * 32 + (lane >> 3) * 8;
    const int tl0 = tlh * 32 + (lane & 7) * 4;
    // Y-combine / epilogue mapping: cp = (tid>>6)*4 + k. Dead cout 16..31
    // <=> cp in [8,16) <=> tid>>6 in {2,3} — whole warps 4..7.
    const bool skipw = PRUNE && (by > 0) && (((tid >> 6) == 2) || ((tid >> 6) == 3));
    const ull ONE2 = pk2(1.f, 1.f), NEG2 = pk2(-1.f, -1.f);
    const int ia_t[4] = {0, 1, 2, 1}, ib_t[4] = {2, 2, 1, 3};
    const float sb_t[4] = {-1.f, 1.f, -1.f, -1.f};
    const float f0_t[4] = {1.f, 1.f, 1.f, 0.f};
    const float f1_t[4] = {0.f, 1.f, -1.f, -1.f};

    auto v_compute = [&](int g) {
        const int ia = ia_t[g], ib = ib_t[g];
        const ull SB = pk2(sb_t[g], sb_t[g]);
        for (int idx = tid; idx < CIN * 64; idx += 512) {
            int tl = idx & 63, ci = idx >> 6;
            int tly = tl >> 5, tlx = tl & 31;
            const float* rb = RAW + ci * 408 + (tly * 2) * 68 + tlx * 2;
            ull e01 = fma2(*(const ull*)(rb + ib * 68), SB, *(const ull*)(rb + ia * 68));
            ull e23 = fma2(*(const ull*)(rb + ib * 68 + 2), SB, *(const ull*)(rb + ia * 68 + 2));
            float e0, e1, e2, e3;
            upk2(e0, e1, e01); upk2(e2, e3, e23);
            float* vb = VS + ci * 68 + tl;
            vb[0]            = e0 - e2;
            vb[CIN * 68]     = e1 + e2;
            vb[2 * CIN * 68] = e2 - e1;
            vb[3 * CIN * 68] = e1 - e3;
        }
    };

    v_compute(0);
    __syncthreads();

    for (int g = 0; g < 4; ++g) {
        {
            ull acc[4][4];
#pragma unroll
            for (int p = 0; p < 4; ++p)
#pragma unroll
                for (int t = 0; t < 4; ++t) acc[p][t] = 0ULL;
            const float* Ub = Ut + ((long)(g * 4 + gv) * CIN) * 64 + co0;
            const float* Vb = VS + gv * CIN * 68 + tl0;
#pragma unroll 4
            for (int ci = 0; ci < CIN; ++ci) {
                const ull* up = (const ull*)(Ub + ci * 64);
                ull u0 = up[0], u1 = up[1], u2 = up[2], u3 = up[3];
                float4 vv = *(const float4*)(Vb + ci * 68);
                ull p0 = pk2(vv.x, vv.x), p1 = pk2(vv.y, vv.y);
                ull p2 = pk2(vv.z, vv.z), p3 = pk2(vv.w, vv.w);
                acc[0][0] = fma2(u0, p0, acc[0][0]); acc[0][1] = fma2(u0, p1, acc[0][1]);
                acc[0][2] = fma2(u0, p2, acc[0][2]); acc[0][3] = fma2(u0, p3, acc[0][3]);
                acc[1][0] = fma2(u1, p0, acc[1][0]); acc[1][1] = fma2(u1, p1, acc[1][1]);
                acc[1][2] = fma2(u1, p2, acc[1][2]); acc[1][3] = fma2(u1, p3, acc[1][3]);
                acc[2][0] = fma2(u2, p0, acc[2][0]); acc[2][1] = fma2(u2, p1, acc[2][1]);
                acc[2][2] = fma2(u2, p2, acc[2][2]); acc[2][3] = fma2(u2, p3, acc[2][3]);
                acc[3][0] = fma2(u3, p0, acc[3][0]); acc[3][1] = fma2(u3, p1, acc[3][1]);
                acc[3][2] = fma2(u3, p2, acc[3][2]); acc[3][3] = fma2(u3, p3, acc[3][3]);
            }
#pragma unroll
            for (int t = 0; t < 4; ++t)
#pragma unroll
                for (int p = 0; p < 4; ++p)
                    *(ull*)(MS + (gv * 64 + tl0 + t) * 66 + co0 + 2 * p) = acc[p][t];
        }
        __syncthreads();
        if (!skipw) {
            const ull F0 = pk2(f0_t[g], f0_t[g]);
            const ull F1 = pk2(f1_t[g], f1_t[g]);
            int tl = tid & 63, cpg = tid >> 6;
#pragma unroll
            for (int k = 0; k < 4; ++k) {
                int cp = cpg * 4 + k;
                const float* mb = MS + tl * 66 + 2 * cp;
                ull m0 = *(const ull*)(mb);
                ull m1 = *(const ull*)(mb + 4224);
                ull m2 = *(const ull*)(mb + 8448);
                ull m3 = *(const ull*)(mb + 12672);
                ull z0 = fma2(m2, ONE2, fma2(m1, ONE2, m0));
                ull z1 = fma2(m3, NEG2, fma2(m2, NEG2, m1));
                Y[k][0] = fma2(z0, F0, Y[k][0]);
                Y[k][1] = fma2(z1, F0, Y[k][1]);
                Y[k][2] = fma2(z0, F1, Y[k][2]);
                Y[k][3] = fma2(z1, F1, Y[k][3]);
            }
        }
        if (g < 3) v_compute(g + 1);
        __syncthreads();
    }
    if (!skipw) {
        int tl = tid & 63, cpg = tid >> 6;
        int tly = tl >> 5, tlx = tl & 31;
#pragma unroll
        for (int k = 0; k < 4; ++k) {
            int cp = cpg * 4 + k;
            float b0 = BS[2 * cp], b1 = BS[2 * cp + 1];
#pragma unroll
            for (int i = 0; i < 2; ++i)
#pragma unroll
                for (int j = 0; j < 2; ++j) {
                    float v0, v1;
                    upk2(v0, v1, Y[k][i * 2 + j]);
                    v0 += b0; v1 += b1;
                    if (ACT == 1) { v0 = fmaxf(v0, 0.f); v1 = fmaxf(v1, 0.f); }
                    else          { v0 = tanhf(v0);      v1 = tanhf(v1); }
                    int py = by * 4 + tly * 2 + i;
                    int px = bx * 64 + tlx * 2 + j;
                    dst[((long)(n * 64 + 2 * cp) * 512 + py) * 512 + px]     = v0;
                    dst[((long)(n * 64 + 2 * cp + 1) * 512 + py) * 512 + px] = v1;
                }
        }
    }
}

// ---------------- pool / upsample ----------------
__global__ void maxpool_kernel(const float* __restrict__ src, float* __restrict__ dst,
                               int C, int Ho, int Wo, int N)
{
    long idx = (long)blockIdx.x * blockDim.x + threadIdx.x;
    long total = (long)N * C * Ho * Wo;
    if (idx >= total) return;
    int x = (int)(idx % Wo);  long t = idx / Wo;
    int y = (int)(t % Ho);    t /= Ho;
    int c = (int)(t % C);
    int n = (int)(t / C);
    int Hi = Ho * 2, Wi = Wo * 2;
    const float* p = src + (((long)n * C + c) * Hi + 2 * y) * Wi + 2 * x;
    dst[idx] = fmaxf(fmaxf(p[0], p[1]), fmaxf(p[Wi], p[Wi + 1]));
}

__global__ void upsample_kernel(const float* __restrict__ src, float* __restrict__ dst,
                                int C, int Hs, int Ws, int scale,
                                long sBS, long dBS, int N)
{
    int Hd = Hs * scale, Wd = Ws * scale;
    long idx = (long)blockIdx.x * blockDim.x + threadIdx.x;
    long total = (long)N * C * Hd * Wd;
    if (idx >= total) return;
    int x = (int)(idx % Wd);  long t = idx / Wd;
    int y = (int)(t % Hd);    t /= Hd;
    int c = (int)(t % C);
    int n = (int)(t / C);
    float inv = 1.0f / (float)scale;
    float fy = (y + 0.5f) * inv - 0.5f;
    float fx = (x + 0.5f) * inv - 0.5f;
    int y0 = (int)floorf(fy), x0 = (int)floorf(fx);
    float wy = fy - (float)y0, wx = fx - (float)x0;
    int y0c = min(max(y0, 0), Hs - 1), y1c = min(max(y0 + 1, 0), Hs - 1);
    int x0c = min(max(x0, 0), Ws - 1), x1c = min(max(x0 + 1, 0), Ws - 1);
    const float* p = src + n * sBS + (long)c * Hs * Ws;
    float v00 = p[(long)y0c * Ws + x0c], v01 = p[(long)y0c * Ws + x1c];
    float v10 = p[(long)y1c * Ws + x0c], v11 = p[(long)y1c * Ws + x1c];
    float v = (1.f - wy) * ((1.f - wx) * v00 + wx * v01)
            +        wy  * ((1.f - wx) * v10 + wx * v11);
    dst[n * dBS + ((long)c * Hd + y) * Wd + x] = v;
}

// ---------------- scans ----------------
__device__ __forceinline__ float warp_affine_prefix(float& A, float& B, int lane)
{
#pragma unroll
    for (int d = 1; d < 32; d <<= 1) {
        float Ap = __shfl_up_sync(0xffffffffu, A, d);
        float Bp = __shfl_up_sync(0xffffffffu, B, d);
        if (lane >= d) { B = fmaf(A, Bp, B); A *= Ap; }
    }
    float yin = __shfl_up_sync(0xffffffffu, B, 1);
    return (lane == 0) ? 0.0f : yin;
}

__global__ __launch_bounds__(256) void hscan_fused()
{
    int gw = (blockIdx.x * blockDim.x + threadIdx.x) >> 5;
    int lane = threadIdx.x & 31;
    int y = gw % 512;  int t = gw / 512;
    int c = t % 16;    int n = t / 16;
    long rowc = ((long)(n * 16 + c) * 512 + y) * 512;
    const float* a1 = g_pool + O_C9 + ((long)(n * 64 + c)      * 512 + y) * 512;
    const float* a2 = g_pool + O_C9 + ((long)(n * 64 + 32 + c) * 512 + y) * 512;
    const float* u  = g_pool + O_MS + rowc;
    float* hm = g_pool + O_HM + rowc;
    int x0 = lane * 16, mlane = 31 - lane;

    float a1v[16], ufv[16], h1v[16], h2v[16];
#pragma unroll
    for (int k = 0; k < 16; ++k) { a1v[k] = a1[x0 + k]; ufv[k] = u[x0 + k]; }
    float A = 1.f, B = 0.f;
#pragma unroll
    for (int k = 0; k < 16; ++k) {
        float av = a1v[k];
        B = fmaf(av, B, (1.f - av) * ufv[k]);
        A *= av;
    }
    float yv = warp_affine_prefix(A, B, lane);
#pragma unroll
    for (int k = 0; k < 16; ++k) {
        float av = a1v[k];
        yv = fmaf(av, yv, (1.f - av) * ufv[k]);
        h1v[k] = yv;
    }
    float u2v[16];
#pragma unroll
    for (int k = 0; k < 16; ++k)
        u2v[k] = __shfl_sync(0xffffffffu, ufv[15 - k], mlane);
    A = 1.f; B = 0.f;
#pragma unroll
    for (int k = 0; k < 16; ++k) {
        float av = a1v[k];
        B = fmaf(av, B, (1.f - av) * u2v[k]);
        A *= av;
    }
    yv = warp_affine_prefix(A, B, lane);
#pragma unroll
    for (int k = 0; k < 16; ++k) {
        float av = a1v[k];
        yv = fmaf(av, yv, (1.f - av) * u2v[k]);
        h2v[k] = yv;
    }
#pragma unroll
    for (int k = 0; k < 16; ++k) a1v[k] = a2[x0 + k];
    A = 1.f; B = 0.f;
#pragma unroll
    for (int k = 0; k < 16; ++k) {
        float av = a1v[k];
        B = fmaf(av, B, (1.f - av) * h1v[k]);
        A *= av;
    }
    yv = warp_affine_prefix(A, B, lane);
#pragma unroll
    for (int k = 0; k < 16; ++k) {
        float av = a1v[k];
        yv = fmaf(av, yv, (1.f - av) * h1v[k]);
        h1v[k] = yv;
    }
    float u6v[16];
#pragma unroll
    for (int k = 0; k < 16; ++k)
        u6v[k] = __shfl_sync(0xffffffffu, h2v[15 - k], mlane);
    A = 1.f; B = 0.f;
#pragma unroll
    for (int k = 0; k < 16; ++k) {
        float av = a1v[k];
        B = fmaf(av, B, (1.f - av) * u6v[k]);
        A *= av;
    }
    yv = warp_affine_prefix(A, B, lane);
#pragma unroll
    for (int k = 0; k < 16; ++k) {
        float av = a1v[k];
        yv = fmaf(av, yv, (1.f - av) * u6v[k]);
        hm[x0 + k] = fmaxf(h1v[k], yv);
    }
}

__global__ __launch_bounds__(256) void vscan34_blk()
{
    int blk = blockIdx.x;
    int strip = blk & 15;  int t = blk >> 4;
    int c = t & 15;        int n = t >> 4;
    int lx = threadIdx.x & 31, g = threadIdx.x >> 5;
    int x = strip * 32 + lx;
    const float* gx1 = g_pool + O_C9 + (long)(n * 64 + c)      * PX;
    const float* gy1 = g_pool + O_C9 + (long)(n * 64 + 16 + c) * PX;
    const float* u   = g_pool + O_MS + (long)(n * 16 + c) * PX;
    float* h3 = g_pool + O_H3 + (long)(n * 16 + c) * PX;
    float* h4 = g_pool + O_H4 + (long)(n * 16 + c) * PX;
    __shared__ float sA[8][33], s3[8][33], s4[8][33];
    int y0 = g << 6;
    float A = 1.f, B3 = 0.f, B4 = 0.f;
    for (int i = 0; i < 64; ++i) {
        int y = y0 + i;
        float av = (y == 0) ? gy1[x] : gx1[(long)y * 512 + x];
        float om = 1.f - av;
        B3 = fmaf(av, B3, om * u[(long)y * 512 + x]);
        B4 = fmaf(av, B4, om * u[(long)(511 - y) * 512 + x]);
        A *= av;
    }
    sA[g][lx] = A; s3[g][lx] = B3; s4[g][lx] = B4;
    __syncthreads();
    if (g == 0) {
        float p3 = 0.f, p4 = 0.f;
        for (int gg = 0; gg < 8; ++gg) {
            float a_ = sA[gg][lx], b3 = s3[gg][lx], b4 = s4[gg][lx];
            s3[gg][lx] = p3; s4[gg][lx] = p4;
            p3 = fmaf(a_, p3, b3); p4 = fmaf(a_, p4, b4);
        }
    }
    __syncthreads();
    float y3 = s3[g][lx], y4 = s4[g][lx];
    for (int i = 0; i < 64; ++i) {
        int y = y0 + i;
        float av = (y == 0) ? gy1[x] : gx1[(long)y * 512 + x];
        float om = 1.f - av;
        y3 = fmaf(av, y3, om * u[(long)y * 512 + x]);
        h3[(long)y * 512 + x] = y3;
        y4 = fmaf(av, y4, om * u[(long)(511 - y) * 512 + x]);
        h4[(long)y * 512 + x] = y4;
    }
}

__global__ __launch_bounds__(256) void vscan78_blk()
{
    int blk = blockIdx.x;
    int strip = blk & 15;  int t = blk >> 4;
    int c = t & 15;        int n = t >> 4;
    int lx = threadIdx.x & 31, g = threadIdx.x >> 5;
    int x = strip * 32 + lx;
    const float* a  = g_pool + O_C9 + (long)(n * 64 + 48 + c) * PX;
    const float* h3 = g_pool + O_H3 + (long)(n * 16 + c) * PX;
    const float* h4 = g_pool + O_H4 + (long)(n * 16 + c) * PX;
    const float* hm = g_pool + O_HM + (long)(n * 16 + c) * PX;
    float* elt = g_pool + O_ELT + (long)(n * 16 + c) * PX;
    __shared__ float sA[8][33], s7[8][33], s8[8][33];
    int y0 = g << 6;
    float A = 1.f, B7 = 0.f, B8 = 0.f;
    for (int i = 0; i < 64; ++i) {
        int y = y0 + i;
        float av = a[(long)y * 512 + x];
        float om = 1.f - av;
        B7 = fmaf(av, B7, om * h3[(long)y * 512 + x]);
        B8 = fmaf(av, B8, om * h4[(long)(511 - y) * 512 + x]);
        A *= av;
    }
    sA[g][lx] = A; s7[g][lx] = B7; s8[g][lx] = B8;
    __syncthreads();
    if (g == 0) {
        float p7 = 0.f, p8 = 0.f;
        for (int gg = 0; gg < 8; ++gg) {
            float a_ = sA[gg][lx], b7 = s7[gg][lx], b8 = s8[gg][lx];
            s7[gg][lx] = p7; s8[gg][lx] = p8;
            p7 = fmaf(a_, p7, b7); p8 = fmaf(a_, p8, b8);
        }
    }
    __syncthreads();
    float y7 = s7[g][lx], y8 = s8[g][lx];
    for (int i = 0; i < 64; ++i) {
        int y = y0 + i;
        float av = a[(long)y * 512 + x];
        float om = 1.f - av;
        y7 = fmaf(av, y7, om * h3[(long)y * 512 + x]);
        y8 = fmaf(av, y8, om * h4[(long)(511 - y) * 512 + x]);
        elt[(long)y * 512 + x] = fmaxf(hm[(long)y * 512 + x], fmaxf(y7, y8));
    }
}

// ---------------- launch ----------------
static inline int gs(long total, int bs) { return (int)((total + bs - 1) / bs); }

template <int K, int ACT, int CO, int XT>
static void launch_conv(const float* srcA, int ca, const float* srcB, int cb,
                        float* dst, int cout, const float* w, const float* b,
                        int H, int W, int N, cudaStream_t st = 0)
{
    const int BT = 128;
    int WXT = W / XT;
    int nblk = (H * WXT + BT - 1) / BT;
    int coG = (cout + CO - 1) / CO;
    int blocks = N * coG * nblk;
    int smem = (ca + cb) * K * K * CO * (int)sizeof(float);
    conv2d_pk<K, ACT, CO, XT><<<blocks, BT, smem, st>>>(srcA, ca, srcB, cb, dst, cout, w, b, H, W, N, nblk);
}

extern "C" void kernel_launch(void* const* d_in, const int* in_sizes, int n_in,
                              void* d_out, int out_size)
{
    const float* x    = (const float*)d_in[0];
    const float* w_s1 = (const float*)d_in[1];  const float* b_s1 = (const float*)d_in[2];
    const float* w_mc = (const float*)d_in[3];  const float* b_mc = (const float*)d_in[4];
    const float* w2   = (const float*)d_in[5];  const float* b2   = (const float*)d_in[6];
    const float* w3   = (const float*)d_in[7];  const float* b3   = (const float*)d_in[8];
    const float* w4   = (const float*)d_in[9];  const float* b4   = (const float*)d_in[10];
    const float* w5   = (const float*)d_in[11]; const float* b5   = (const float*)d_in[12];
    const float* w6   = (const float*)d_in[13]; const float* b6   = (const float*)d_in[14];
    const float* w6s  = (const float*)d_in[15]; const float* b6s  = (const float*)d_in[16];
    const float* w7   = (const float*)d_in[17]; const float* b7   = (const float*)d_in[18];
    const float* w8   = (const float*)d_in[19]; const float* b8   = (const float*)d_in[20];
    const float* w9   = (const float*)d_in[21]; const float* b9   = (const float*)d_in[22];
    const float* w10  = (const float*)d_in[23]; const float* b10  = (const float*)d_in[24];
    const float* w11  = (const float*)d_in[25]; const float* b11  = (const float*)d_in[26];
    float* out = (float*)d_out;

    float* pool = nullptr;
    cudaGetSymbolAddress((void**)&pool, g_pool);

    static const int SM9  = (32 * 408 + 32 * 272 + 16896 + 64) * 4;
    static const int SM10 = (16 * 408 + 16 * 272 + 16896 + 64) * 4;
    cudaFuncSetAttribute(conv3_wino<32, 2, 1, 1>, cudaFuncAttributeMaxDynamicSharedMemorySize, SM9);
    cudaFuncSetAttribute(conv3_wino<16, 1, 0, 0>, cudaFuncAttributeMaxDynamicSharedMemorySize, SM10);

    static cudaStream_t sideQ = nullptr;
    static cudaEvent_t evFork = nullptr, evJoin = nullptr;
    if (!sideQ) {
        cudaStreamCreateWithFlags(&sideQ, cudaStreamNonBlocking);
        cudaEventCreateWithFlags(&evFork, cudaEventDisableTiming);
        cudaEventCreateWithFlags(&evJoin, cudaEventDisableTiming);
    }

    const int BS = 256;
    const int N = 2;

    // ---- fork: branch A on sideQ ----
    cudaEventRecord(evFork, 0);
    cudaStreamWaitEvent(sideQ, evFork, 0);

    wino_filt<<<gs(64 * 32, BS), BS, 0, sideQ>>>(w9, pool + O_U9, 32);
    wino_filt<<<gs(64 * 16, BS), BS, 0, sideQ>>>(w10, pool + O_U10, 16);
    launch_conv<3, 0, 4, 8>(x, 3, nullptr, 0, pool + O_S1, 3, w_s1, b_s1, 512, 512, N, sideQ);
    maxpool_kernel<<<gs((long)N * 3 * 256 * 256, BS), BS, 0, sideQ>>>(pool + O_S1, pool + O_S2, 3, 256, 256, N);
    maxpool_kernel<<<gs((long)N * 3 * 128 * 128, BS), BS, 0, sideQ>>>(pool + O_S2, pool + O_S3, 3, 128, 128, N);
    maxpool_kernel<<<gs((long)N * 3 * 64 * 64, BS), BS, 0, sideQ>>>(pool + O_S3, pool + O_S4, 3, 64, 64, N);
    for (int n = 0; n < N; ++n)
        cudaMemcpyAsync(pool + O_MULTI + (long)n * 12 * PX, pool + O_S1 + (long)n * 3 * PX,
                        3 * PX * sizeof(float), cudaMemcpyDeviceToDevice, sideQ);
    upsample_kernel<<<gs((long)N * 3 * PX, BS), BS, 0, sideQ>>>(pool + O_S2, pool + O_MULTI + 3 * PX,
        3, 256, 256, 2, 3 * (PX / 4), 12 * PX, N);
    upsample_kernel<<<gs((long)N * 3 * PX, BS), BS, 0, sideQ>>>(pool + O_S3, pool + O_MULTI + 6 * PX,
        3, 128, 128, 4, 3 * (PX / 16), 12 * PX, N);
    upsample_kernel<<<gs((long)N * 3 * PX, BS), BS, 0, sideQ>>>(pool + O_S4, pool + O_MULTI + 9 * PX,
        3, 64, 64, 8, 3 * (PX / 64), 12 * PX, N);
    launch_conv<3, 0, 8, 8>(pool + O_MULTI, 12, nullptr, 0, pool + O_MS, 16, w_mc, b_mc, 512, 512, N, sideQ);
    cudaEventRecord(evJoin, sideQ);

    // ---- branch B: c2 + encoder/decoder ----
    launch_conv<5, 1, 8, 4>(x, 3, nullptr, 0, pool + O_C2, 16, w2, b2, 512, 512, N);
    maxpool_kernel<<<gs((long)N * 16 * 256 * 256, BS), BS>>>(pool + O_C2, pool + O_C2P, 16, 256, 256, N);
    launch_conv<3, 1, 8, 8>(pool + O_C2P, 16, nullptr, 0, pool + O_C3, 32, w3, b3, 256, 256, N);
    maxpool_kernel<<<gs((long)N * 32 * 128 * 128, BS), BS>>>(pool + O_C3, pool + O_C3P, 32, 128, 128, N);
    launch_conv<3, 1, 8, 8>(pool + O_C3P, 32, nullptr, 0, pool + O_C4, 32, w4, b4, 128, 128, N);
    maxpool_kernel<<<gs((long)N * 32 * 64 * 64, BS), BS>>>(pool + O_C4, pool + O_C4P, 32, 64, 64, N);
    launch_conv<3, 1, 8, 4>(pool + O_C4P, 32, nullptr, 0, pool + O_C5, 32, w5, b5, 64, 64, N);
    maxpool_kernel<<<gs((long)N * 32 * 32 * 32, BS), BS>>>(pool + O_C5, pool + O_C5P, 32, 32, 32, N);
    launch_conv<3, 1, 8, 4>(pool + O_C5P, 32, nullptr, 0, pool + O_C6, 64, w6, b6, 32, 32, N);
    upsample_kernel<<<gs((long)N * 64 * 64 * 64, BS), BS>>>(pool + O_C6, pool + O_C6U,
        64, 32, 32, 2, 64L * 32 * 32, 64L * 64 * 64, N);
    launch_conv<3, 1, 8, 4>(pool + O_C6U, 64, nullptr, 0, pool + O_C6S, 64, w6s, b6s, 64, 64, N);
    upsample_kernel<<<gs((long)N * 64 * 128 * 128, BS), BS>>>(pool + O_C6S, pool + O_C6RE,
        64, 64, 64, 2, 64L * 64 * 64, 64L * 128 * 128, N);
    launch_conv<3, 1, 8, 8>(pool + O_C6RE, 64, pool + O_C4, 32, pool + O_C7C, 32, w7, b7, 128, 128, N);
    upsample_kernel<<<gs((long)N * 32 * 256 * 256, BS), BS>>>(pool + O_C7C, pool + O_C7,
        32, 128, 128, 2, 32L * 128 * 128, 32L * 256 * 256, N);
    launch_conv<3, 1, 8, 8>(pool + O_C7, 32, pool + O_C3, 32, pool + O_C8C, 16, w8, b8, 256, 256, N);
    // c8 upsample fused into conv3_wino below

    // ---- join ----
    cudaStreamWaitEvent(0, evJoin, 0);

    {
        dim3 grid(8, 128, N);
        conv3_wino<32, 2, 1, 1><<<grid, 512, SM9>>>(pool + O_C8C, 16, pool + O_C2,
                                                    pool + O_U9, b9, pool + O_C9);
    }
    hscan_fused<<<2048, 256>>>();
    vscan34_blk<<<512, 256>>>();
    vscan78_blk<<<512, 256>>>();
    {
        dim3 grid(8, 128, N);
        conv3_wino<16, 1, 0, 0><<<grid, 512, SM10>>>(pool + O_ELT, 16, nullptr,
                                                     pool + O_U10, b10, pool + O_C10);
    }
    launch_conv<3, 1, 4, 8>(pool + O_C10, 64, nullptr, 0, out, 3, w11, b11, 512, 512, N);
}

// round 17
// speedup vs baseline: 1.1821x; 1.0142x over previous
#include <cuda_runtime.h>
#include <math.h>
#include <stdint.h>

static constexpr long PX = 512L * 512;
static constexpr long O_S1    = 0;
static constexpr long O_S2    = O_S1    + 6 * PX;
static constexpr long O_S3    = O_S2    + 6 * (PX / 4);
static constexpr long O_S4    = O_S3    + 6 * (PX / 16);
static constexpr long O_MULTI = O_S4    + 6 * (PX / 64);
static constexpr long O_MS    = O_MULTI + 24 * PX;
static constexpr long O_C2    = O_MS    + 32 * PX;
static constexpr long O_C2P   = O_C2    + 32 * PX;
static constexpr long O_C3    = O_C2P   + 32 * (PX / 4);
static constexpr long O_C3P   = O_C3    + 64 * (PX / 4);
static constexpr long O_C4    = O_C3P   + 64 * (PX / 16);
static constexpr long O_C4P   = O_C4    + 64 * (PX / 16);
static constexpr long O_C5    = O_C4P   + 64 * (PX / 64);
static constexpr long O_C5P   = O_C5    + 64 * (PX / 64);
static constexpr long O_C6    = O_C5P   + 64 * (PX / 256);
static constexpr long O_C6U   = O_C6    + 128 * (PX / 256);
static constexpr long O_C6S   = O_C6U   + 128 * (PX / 64);
static constexpr long O_C6RE  = O_C6S   + 128 * (PX / 64);
static constexpr long O_C7C   = O_C6RE  + 128 * (PX / 16);
static constexpr long O_C7    = O_C7C   + 64 * (PX / 16);
static constexpr long O_C8C   = O_C7    + 64 * (PX / 4);
static constexpr long O_C8    = O_C8C   + 32 * (PX / 4);
static constexpr long O_C9    = O_C8    + 32 * PX;
static constexpr long O_H3    = O_C9    + 128 * PX;
static constexpr long O_H4    = O_H3    + 32 * PX;
static constexpr long O_HM    = O_H4    + 32 * PX;
static constexpr long O_ELT   = O_HM    + 32 * PX;
static constexpr long O_C10   = O_ELT   + 32 * PX;
static constexpr long O_U9    = O_C10   + 128 * PX;
static constexpr long O_U10   = O_U9    + 32768;
static constexpr long POOL_TOTAL = O_U10 + 16384;

__device__ float g_pool[POOL_TOTAL];

typedef unsigned long long ull;
__device__ __forceinline__ ull pk2(float lo, float hi) {
    ull r; asm("mov.b64 %0, {%1, %2};" : "=l"(r) : "f"(lo), "f"(hi)); return r;
}
__device__ __forceinline__ void upk2(float& lo, float& hi, ull v) {
    asm("mov.b64 {%0, %1}, %2;" : "=f"(lo), "=f"(hi) : "l"(v));
}
__device__ __forceinline__ ull fma2(ull a, ull b, ull c) {
    ull d; asm("fma.rn.f32x2 %0, %1, %2, %3;" : "=l"(d) : "l"(a), "l"(b), "l"(c)); return d;
}

// ---------------- fp32 direct conv (vectorized interior loads) ----------------
template <int K, int ACT, int CO, int XT>
__global__ __launch_bounds__(128)
void conv2d_pk(const float* __restrict__ srcA, int ca,
               const float* __restrict__ srcB, int cb,
               float* __restrict__ dst, int cout,
               const float* __restrict__ w, const float* __restrict__ bias,
               int H, int W, int N, int nblk)
{
    extern __shared__ float w_s[];
    const int ctot = ca + cb;
    const int coG = (cout + CO - 1) / CO;
    int blk = blockIdx.x;
    int pblk = blk % nblk;
    int cog  = (blk / nblk) % coG;
    int n    = blk / (nblk * coG);
    int co0  = cog * CO;
    const int nw = ctot * K * K;
    for (int i = threadIdx.x; i < nw * CO; i += blockDim.x) {
        int e = i / CO, j = i - e * CO, co = co0 + j;
        w_s[i] = (co < cout) ? __ldg(w + (long)co * nw + e) : 0.0f;
    }
    __syncthreads();
    const int WXT = W / XT;
    int pos = pblk * blockDim.x + threadIdx.x;
    if (pos >= H * WXT) return;
    int y = pos / WXT, x0 = (pos % WXT) * XT;
    constexpr int P = K / 2, CP = CO / 2, NV = K + XT - 1;
    ull acc[CP][XT];
#pragma unroll
    for (int cp = 0; cp < CP; ++cp) {
        float b0 = (co0 + 2 * cp < cout) ? __ldg(bias + co0 + 2 * cp) : 0.0f;
        float b1 = (co0 + 2 * cp + 1 < cout) ? __ldg(bias + co0 + 2 * cp + 1) : 0.0f;
        ull bp = pk2(b0, b1);
#pragma unroll
        for (int m = 0; m < XT; ++m) acc[cp][m] = bp;
    }
    bool lok[P], rok[K - 1 - P];
#pragma unroll
    for (int i = 0; i < P; ++i) lok[i] = (x0 - P + i >= 0);
#pragma unroll
    for (int i = 0; i < K - 1 - P; ++i) rok[i] = (x0 + XT + i < W);

    for (int ci = 0; ci < ctot; ++ci) {
        const float* plane = (ci < ca)
            ? srcA + ((long)n * ca + ci) * H * W
            : srcB + ((long)n * cb + (ci - ca)) * H * W;
        const float* ws = w_s + ci * (K * K * CO);
#pragma unroll
        for (int ky = 0; ky < K; ++ky) {
            int yy = y + ky - P;
            if (yy < 0 || yy >= H) continue;
            const float* rp = plane + (long)yy * W + x0;
            float vf[NV];
#pragma unroll
            for (int q = 0; q < XT / 4; ++q) {
                float4 t = *reinterpret_cast<const float4*>(rp + 4 * q);
                vf[P + 4 * q]     = t.x;
                vf[P + 4 * q + 1] = t.y;
                vf[P + 4 * q + 2] = t.z;
                vf[P + 4 * q + 3] = t.w;
            }
#pragma unroll
            for (int i = 0; i < P; ++i)
                vf[i] = lok[i] ? __ldg(rp + i - P) : 0.0f;
#pragma unroll
            for (int i = 0; i < K - 1 - P; ++i)
                vf[P + XT + i] = rok[i] ? __ldg(rp + XT + i) : 0.0f;

            ull pv[NV];
#pragma unroll
            for (int i = 0; i < NV; ++i) pv[i] = pk2(vf[i], vf[i]);
#pragma unroll
            for (int kx = 0; kx < K; ++kx) {
                const float* we = ws + (ky * K + kx) * CO;
#pragma unroll
                for (int cp = 0; cp < CP; ++cp) {
                    ull wv = *reinterpret_cast<const ull*>(we + 2 * cp);
#pragma unroll
                    for (int m = 0; m < XT; ++m)
                        acc[cp][m] = fma2(wv, pv[kx + m], acc[cp][m]);
                }
            }
        }
    }
#pragma unroll
    for (int cp = 0; cp < CP; ++cp) {
        float o0[XT], o1[XT];
#pragma unroll
        for (int m = 0; m < XT; ++m) upk2(o0[m], o1[m], acc[cp][m]);
#pragma unroll
        for (int h = 0; h < 2; ++h) {
            int co = co0 + 2 * cp + h;
            if (co >= cout) break;
            float* ov = h ? o1 : o0;
#pragma unroll
            for (int m = 0; m < XT; ++m) {
                if (ACT == 1) ov[m] = fmaxf(ov[m], 0.f);
                else if (ACT == 2) ov[m] = tanhf(ov[m]);
            }
            long o = (((long)n * cout + co) * H + y) * W + x0;
#pragma unroll
            for (int q = 0; q < XT / 4; ++q)
                *reinterpret_cast<float4*>(dst + o + 4 * q) =
                    make_float4(ov[4 * q], ov[4 * q + 1], ov[4 * q + 2], ov[4 * q + 3]);
        }
    }
}

// ---------------- Winograd filter transform ----------------
__global__ void wino_filt(const float* __restrict__ w, float* __restrict__ Ut, int CIN)
{
    int idx = blockIdx.x * blockDim.x + threadIdx.x;
    if (idx >= 64 * CIN) return;
    int co = idx / CIN, ci = idx % CIN;
    const float* gp = w + (co * CIN + ci) * 9;
    float g[3][3];
#pragma unroll
    for (int i = 0; i < 3; ++i)
#pragma unroll
        for (int j = 0; j < 3; ++j) g[i][j] = __ldg(gp + i * 3 + j);
    float Gg[4][3];
#pragma unroll
    for (int c = 0; c < 3; ++c) {
        Gg[0][c] = g[0][c];
        Gg[1][c] = 0.5f * (g[0][c] + g[1][c] + g[2][c]);
        Gg[2][c] = 0.5f * (g[0][c] - g[1][c] + g[2][c]);
        Gg[3][c] = g[2][c];
    }
#pragma unroll
    for (int u = 0; u < 4; ++u) {
        float U0 = Gg[u][0];
        float U1 = 0.5f * (Gg[u][0] + Gg[u][1] + Gg[u][2]);
        float U2 = 0.5f * (Gg[u][0] - Gg[u][1] + Gg[u][2]);
        float U3 = Gg[u][2];
        Ut[((u * 4 + 0) * CIN + ci) * 64 + co] = U0;
        Ut[((u * 4 + 1) * CIN + ci) * 64 + co] = U1;
        Ut[((u * 4 + 2) * CIN + ci) * 64 + co] = U2;
        Ut[((u * 4 + 3) * CIN + ci) * 64 + co] = U3;
    }
}

// ---------------- Fused Winograd conv ----------------
template <int CIN, int ACT, int UPS, int PRUNE>
__global__ __launch_bounds__(512, 1)
void conv3_wino(const float* __restrict__ srcA, int ca,
                const float* __restrict__ srcB,
                const float* __restrict__ Ut,
                const float* __restrict__ bias,
                float* __restrict__ dst)
{
    extern __shared__ float sm[];
    float* RAW = sm;
    float* VS  = sm + CIN * 408;
    float* MS  = VS + CIN * 272;
    float* BS  = MS + 16896;
    const int tid = threadIdx.x;
    const int bx = blockIdx.x, by = blockIdx.y, n = blockIdx.z;
    if (tid < 64) BS[tid] = __ldg(bias + tid);

    for (int i = tid; i < CIN * 396; i += 512) {
        int c = i % 66, rr = (i / 66) % 6, ci = i / 396;
        int px = bx * 64 + c - 1, py = by * 4 + rr - 1;
        float v = 0.0f;
        if (px >= 0 && px < 512 && py >= 0 && py < 512) {
            if (UPS && ci < ca) {
                int ys = (py - 1) >> 1, xs = (px - 1) >> 1;
                float wy = (py & 1) ? 0.25f : 0.75f;
                float wx = (px & 1) ? 0.25f : 0.75f;
                int y0c = max(ys, 0), y1c = min(ys + 1, 255);
                int x0c = max(xs, 0), x1c = min(xs + 1, 255);
                const float* p = srcA + (long)(n * ca + ci) * 65536;
                float v00 = __ldg(p + y0c * 256 + x0c);
                float v01 = __ldg(p + y0c * 256 + x1c);
                float v10 = __ldg(p + y1c * 256 + x0c);
                float v11 = __ldg(p + y1c * 256 + x1c);
                v = (1.f - wy) * ((1.f - wx) * v00 + wx * v01)
                  +        wy  * ((1.f - wx) * v10 + wx * v11);
            } else {
                const float* p = (ci < ca)
                    ? srcA + ((long)(n * ca + ci) * 512 + py) * 512 + px
                    : srcB + ((long)(n * (CIN - ca) + (ci - ca)) * 512 + py) * 512 + px;
                v = __ldg(p);
            }
        }
        RAW[ci * 408 + rr * 68 + c] = v;
    }
    __syncthreads();

    ull Y[4][4];
#pragma unroll
    for (int k = 0; k < 4; ++k)
#pragma unroll
        for (int q = 0; q < 4; ++q) Y[k][q] = 0ULL;

    const int lane = tid & 31, wp = tid >> 5;
    const int gv = wp >> 2, coh = (wp >> 1) & 1, tlh = wp & 1;
    const int co0 = coh * 32 + (lane >> 3) * 8;
    const int tl0 = tlh * 32 + (lane & 7) * 4;
    const bool skipw = PRUNE && (by > 0) && (((tid >> 6) == 2) || ((tid >> 6) == 3));
    const ull ONE2 = pk2(1.f, 1.f), NEG2 = pk2(-1.f, -1.f);
    const int ia_t[4] = {0, 1, 2, 1}, ib_t[4] = {2, 2, 1, 3};
    const float sb_t[4] = {-1.f, 1.f, -1.f, -1.f};
    const float f0_t[4] = {1.f, 1.f, 1.f, 0.f};
    const float f1_t[4] = {0.f, 1.f, -1.f, -1.f};

    auto v_compute = [&](int g) {
        const int ia = ia_t[g], ib = ib_t[g];
        const ull SB = pk2(sb_t[g], sb_t[g]);
        for (int idx = tid; idx < CIN * 64; idx += 512) {
            int tl = idx & 63, ci = idx >> 6;
            int tly = tl >> 5, tlx = tl & 31;
            const float* rb = RAW + ci * 408 + (tly * 2) * 68 + tlx * 2;
            ull e01 = fma2(*(const ull*)(rb + ib * 68), SB, *(const ull*)(rb + ia * 68));
            ull e23 = fma2(*(const ull*)(rb + ib * 68 + 2), SB, *(const ull*)(rb + ia * 68 + 2));
            float e0, e1, e2, e3;
            upk2(e0, e1, e01); upk2(e2, e3, e23);
            float* vb = VS + ci * 68 + tl;
            vb[0]            = e0 - e2;
            vb[CIN * 68]     = e1 + e2;
            vb[2 * CIN * 68] = e2 - e1;
            vb[3 * CIN * 68] = e1 - e3;
        }
    };

    v_compute(0);
    __syncthreads();

    for (int g = 0; g < 4; ++g) {
        {
            ull acc[4][4];
#pragma unroll
            for (int p = 0; p < 4; ++p)
#pragma unroll
                for (int t = 0; t < 4; ++t) acc[p][t] = 0ULL;
            const float* Ub = Ut + ((long)(g * 4 + gv) * CIN) * 64 + co0;
            const float* Vb = VS + gv * CIN * 68 + tl0;
#pragma unroll 8
            for (int ci = 0; ci < CIN; ++ci) {
                const ull* up = (const ull*)(Ub + ci * 64);
                ull u0 = up[0], u1 = up[1], u2 = up[2], u3 = up[3];
                float4 vv = *(const float4*)(Vb + ci * 68);
                ull p0 = pk2(vv.x, vv.x), p1 = pk2(vv.y, vv.y);
                ull p2 = pk2(vv.z, vv.z), p3 = pk2(vv.w, vv.w);
                acc[0][0] = fma2(u0, p0, acc[0][0]); acc[0][1] = fma2(u0, p1, acc[0][1]);
                acc[0][2] = fma2(u0, p2, acc[0][2]); acc[0][3] = fma2(u0, p3, acc[0][3]);
                acc[1][0] = fma2(u1, p0, acc[1][0]); acc[1][1] = fma2(u1, p1, acc[1][1]);
                acc[1][2] = fma2(u1, p2, acc[1][2]); acc[1][3] = fma2(u1, p3, acc[1][3]);
                acc[2][0] = fma2(u2, p0, acc[2][0]); acc[2][1] = fma2(u2, p1, acc[2][1]);
                acc[2][2] = fma2(u2, p2, acc[2][2]); acc[2][3] = fma2(u2, p3, acc[2][3]);
                acc[3][0] = fma2(u3, p0, acc[3][0]); acc[3][1] = fma2(u3, p1, acc[3][1]);
                acc[3][2] = fma2(u3, p2, acc[3][2]); acc[3][3] = fma2(u3, p3, acc[3][3]);
            }
#pragma unroll
            for (int t = 0; t < 4; ++t)
#pragma unroll
                for (int p = 0; p < 4; ++p)
                    *(ull*)(MS + (gv * 64 + tl0 + t) * 66 + co0 + 2 * p) = acc[p][t];
        }
        __syncthreads();
        if (!skipw) {
            const ull F0 = pk2(f0_t[g], f0_t[g]);
            const ull F1 = pk2(f1_t[g], f1_t[g]);
            int tl = tid & 63, cpg = tid >> 6;
#pragma unroll
            for (int k = 0; k < 4; ++k) {
                int cp = cpg * 4 + k;
                const float* mb = MS + tl * 66 + 2 * cp;
                ull m0 = *(const ull*)(mb);
                ull m1 = *(const ull*)(mb + 4224);
                ull m2 = *(const ull*)(mb + 8448);
                ull m3 = *(const ull*)(mb + 12672);
                ull z0 = fma2(m2, ONE2, fma2(m1, ONE2, m0));
                ull z1 = fma2(m3, NEG2, fma2(m2, NEG2, m1));
                Y[k][0] = fma2(z0, F0, Y[k][0]);
                Y[k][1] = fma2(z1, F0, Y[k][1]);
                Y[k][2] = fma2(z0, F1, Y[k][2]);
                Y[k][3] = fma2(z1, F1, Y[k][3]);
            }
        }
        if (g < 3) v_compute(g + 1);
        __syncthreads();
    }
    if (!skipw) {
        int tl = tid & 63, cpg = tid >> 6;
        int tly = tl >> 5, tlx = tl & 31;
#pragma unroll
        for (int k = 0; k < 4; ++k) {
            int cp = cpg * 4 + k;
            float b0 = BS[2 * cp], b1 = BS[2 * cp + 1];
#pragma unroll
            for (int i = 0; i < 2; ++i)
#pragma unroll
                for (int j = 0; j < 2; ++j) {
                    float v0, v1;
                    upk2(v0, v1, Y[k][i * 2 + j]);
                    v0 += b0; v1 += b1;
                    if (ACT == 1) { v0 = fmaxf(v0, 0.f); v1 = fmaxf(v1, 0.f); }
                    else          { v0 = tanhf(v0);      v1 = tanhf(v1); }
                    int py = by * 4 + tly * 2 + i;
                    int px = bx * 64 + tlx * 2 + j;
                    dst[((long)(n * 64 + 2 * cp) * 512 + py) * 512 + px]     = v0;
                    dst[((long)(n * 64 + 2 * cp + 1) * 512 + py) * 512 + px] = v1;
                }
        }
    }
}

// ---------------- pool / upsample ----------------
__global__ void maxpool_kernel(const float* __restrict__ src, float* __restrict__ dst,
                               int C, int Ho, int Wo, int N)
{
    long idx = (long)blockIdx.x * blockDim.x + threadIdx.x;
    long total = (long)N * C * Ho * Wo;
    if (idx >= total) return;
    int x = (int)(idx % Wo);  long t = idx / Wo;
    int y = (int)(t % Ho);    t /= Ho;
    int c = (int)(t % C);
    int n = (int)(t / C);
    int Hi = Ho * 2, Wi = Wo * 2;
    const float* p = src + (((long)n * C + c) * Hi + 2 * y) * Wi + 2 * x;
    dst[idx] = fmaxf(fmaxf(p[0], p[1]), fmaxf(p[Wi], p[Wi + 1]));
}

__global__ void upsample_kernel(const float* __restrict__ src, float* __restrict__ dst,
                                int C, int Hs, int Ws, int scale,
                                long sBS, long dBS, int N)
{
    int Hd = Hs * scale, Wd = Ws * scale;
    long idx = (long)blockIdx.x * blockDim.x + threadIdx.x;
    long total = (long)N * C * Hd * Wd;
    if (idx >= total) return;
    int x = (int)(idx % Wd);  long t = idx / Wd;
    int y = (int)(t % Hd);    t /= Hd;
    int c = (int)(t % C);
    int n = (int)(t / C);
    float inv = 1.0f / (float)scale;
    float fy = (y + 0.5f) * inv - 0.5f;
    float fx = (x + 0.5f) * inv - 0.5f;
    int y0 = (int)floorf(fy), x0 = (int)floorf(fx);
    float wy = fy - (float)y0, wx = fx - (float)x0;
    int y0c = min(max(y0, 0), Hs - 1), y1c = min(max(y0 + 1, 0), Hs - 1);
    int x0c = min(max(x0, 0), Ws - 1), x1c = min(max(x0 + 1, 0), Ws - 1);
    const float* p = src + n * sBS + (long)c * Hs * Ws;
    float v00 = p[(long)y0c * Ws + x0c], v01 = p[(long)y0c * Ws + x1c];
    float v10 = p[(long)y1c * Ws + x0c], v11 = p[(long)y1c * Ws + x1c];
    float v = (1.f - wy) * ((1.f - wx) * v00 + wx * v01)
            +        wy  * ((1.f - wx) * v10 + wx * v11);
    dst[n * dBS + ((long)c * Hd + y) * Wd + x] = v;
}

// ---------------- scans ----------------
__device__ __forceinline__ float warp_affine_prefix(float& A, float& B, int lane)
{
#pragma unroll
    for (int d = 1; d < 32; d <<= 1) {
        float Ap = __shfl_up_sync(0xffffffffu, A, d);
        float Bp = __shfl_up_sync(0xffffffffu, B, d);
        if (lane >= d) { B = fmaf(A, Bp, B); A *= Ap; }
    }
    float yin = __shfl_up_sync(0xffffffffu, B, 1);
    return (lane == 0) ? 0.0f : yin;
}

__device__ __forceinline__ void ld16(float* v, const float* p)
{
#pragma unroll
    for (int q = 0; q < 4; ++q) {
        float4 t = *reinterpret_cast<const float4*>(p + 4 * q);
        v[4 * q] = t.x; v[4 * q + 1] = t.y; v[4 * q + 2] = t.z; v[4 * q + 3] = t.w;
    }
}

__global__ __launch_bounds__(256) void hscan_fused()
{
    int gw = (blockIdx.x * blockDim.x + threadIdx.x) >> 5;
    int lane = threadIdx.x & 31;
    int y = gw % 512;  int t = gw / 512;
    int c = t % 16;    int n = t / 16;
    long rowc = ((long)(n * 16 + c) * 512 + y) * 512;
    const float* a1 = g_pool + O_C9 + ((long)(n * 64 + c)      * 512 + y) * 512;
    const float* a2 = g_pool + O_C9 + ((long)(n * 64 + 32 + c) * 512 + y) * 512;
    const float* u  = g_pool + O_MS + rowc;
    float* hm = g_pool + O_HM + rowc;
    int x0 = lane * 16, mlane = 31 - lane;

    float a1v[16], ufv[16], h1v[16], h2v[16];
    ld16(a1v, a1 + x0);
    ld16(ufv, u + x0);
    float A = 1.f, B = 0.f;
#pragma unroll
    for (int k = 0; k < 16; ++k) {
        float av = a1v[k];
        B = fmaf(av, B, (1.f - av) * ufv[k]);
        A *= av;
    }
    float yv = warp_affine_prefix(A, B, lane);
#pragma unroll
    for (int k = 0; k < 16; ++k) {
        float av = a1v[k];
        yv = fmaf(av, yv, (1.f - av) * ufv[k]);
        h1v[k] = yv;
    }
    float u2v[16];
#pragma unroll
    for (int k = 0; k < 16; ++k)
        u2v[k] = __shfl_sync(0xffffffffu, ufv[15 - k], mlane);
    A = 1.f; B = 0.f;
#pragma unroll
    for (int k = 0; k < 16; ++k) {
        float av = a1v[k];
        B = fmaf(av, B, (1.f - av) * u2v[k]);
        A *= av;
    }
    yv = warp_affine_prefix(A, B, lane);
#pragma unroll
    for (int k = 0; k < 16; ++k) {
        float av = a1v[k];
        yv = fmaf(av, yv, (1.f - av) * u2v[k]);
        h2v[k] = yv;
    }
    ld16(a1v, a2 + x0);
    A = 1.f; B = 0.f;
#pragma unroll
    for (int k = 0; k < 16; ++k) {
        float av = a1v[k];
        B = fmaf(av, B, (1.f - av) * h1v[k]);
        A *= av;
    }
    yv = warp_affine_prefix(A, B, lane);
#pragma unroll
    for (int k = 0; k < 16; ++k) {
        float av = a1v[k];
        yv = fmaf(av, yv, (1.f - av) * h1v[k]);
        h1v[k] = yv;
    }
    float u6v[16];
#pragma unroll
    for (int k = 0; k < 16; ++k)
        u6v[k] = __shfl_sync(0xffffffffu, h2v[15 - k], mlane);
    A = 1.f; B = 0.f;
#pragma unroll
    for (int k = 0; k < 16; ++k) {
        float av = a1v[k];
        B = fmaf(av, B, (1.f - av) * u6v[k]);
        A *= av;
    }
    yv = warp_affine_prefix(A, B, lane);
#pragma unroll
    for (int k = 0; k < 16; ++k) {
        float av = a1v[k];
        yv = fmaf(av, yv, (1.f - av) * u6v[k]);
        hm[x0 + k] = fmaxf(h1v[k], yv);
    }
}

// fused vertical scans: phase A (h3/h4 -> gmem), syncthreads, phase B (elt).
// Each block owns a full 32-column strip, so phase B's h3/h4 reads are
// same-block productions; __syncthreads orders them.
__global__ __launch_bounds__(256) void vscan_all()
{
    int blk = blockIdx.x;
    int strip = blk & 15;  int t = blk >> 4;
    int c = t & 15;        int n = t >> 4;
    int lx = threadIdx.x & 31, g = threadIdx.x >> 5;
    int x = strip * 32 + lx;
    const float* gx1 = g_pool + O_C9 + (long)(n * 64 + c)      * PX;
    const float* gy1 = g_pool + O_C9 + (long)(n * 64 + 16 + c) * PX;
    const float* gy2 = g_pool + O_C9 + (long)(n * 64 + 48 + c) * PX;
    const float* u   = g_pool + O_MS + (long)(n * 16 + c) * PX;
    const float* hm  = g_pool + O_HM + (long)(n * 16 + c) * PX;
    float* h3 = g_pool + O_H3 + (long)(n * 16 + c) * PX;
    float* h4 = g_pool + O_H4 + (long)(n * 16 + c) * PX;
    float* elt = g_pool + O_ELT + (long)(n * 16 + c) * PX;
    __shared__ float sA[8][33], s1[8][33], s2[8][33];
    int y0 = g << 6;

    // phase A
    float A = 1.f, B3 = 0.f, B4 = 0.f;
    for (int i = 0; i < 64; ++i) {
        int y = y0 + i;
        float av = (y == 0) ? gy1[x] : gx1[(long)y * 512 + x];
        float om = 1.f - av;
        B3 = fmaf(av, B3, om * u[(long)y * 512 + x]);
        B4 = fmaf(av, B4, om * u[(long)(511 - y) * 512 + x]);
        A *= av;
    }
    sA[g][lx] = A; s1[g][lx] = B3; s2[g][lx] = B4;
    __syncthreads();
    if (g == 0) {
        float p3 = 0.f, p4 = 0.f;
        for (int gg = 0; gg < 8; ++gg) {
            float a_ = sA[gg][lx], b3 = s1[gg][lx], b4 = s2[gg][lx];
            s1[gg][lx] = p3; s2[gg][lx] = p4;
            p3 = fmaf(a_, p3, b3); p4 = fmaf(a_, p4, b4);
        }
    }
    __syncthreads();
    float y3 = s1[g][lx], y4 = s2[g][lx];
    for (int i = 0; i < 64; ++i) {
        int y = y0 + i;
        float av = (y == 0) ? gy1[x] : gx1[(long)y * 512 + x];
        float om = 1.f - av;
        y3 = fmaf(av, y3, om * u[(long)y * 512 + x]);
        h3[(long)y * 512 + x] = y3;
        y4 = fmaf(av, y4, om * u[(long)(511 - y) * 512 + x]);
        h4[(long)y * 512 + x] = y4;
    }
    __syncthreads();

    // phase B
    A = 1.f; float B7 = 0.f, B8 = 0.f;
    for (int i = 0; i < 64; ++i) {
        int y = y0 + i;
        float av = gy2[(long)y * 512 + x];
        float om = 1.f - av;
        B7 = fmaf(av, B7, om * h3[(long)y * 512 + x]);
        B8 = fmaf(av, B8, om * h4[(long)(511 - y) * 512 + x]);
        A *= av;
    }
    sA[g][lx] = A; s1[g][lx] = B7; s2[g][lx] = B8;
    __syncthreads();
    if (g == 0) {
        float p7 = 0.f, p8 = 0.f;
        for (int gg = 0; gg < 8; ++gg) {
            float a_ = sA[gg][lx], b7 = s1[gg][lx], b8 = s2[gg][lx];
            s1[gg][lx] = p7; s2[gg][lx] = p8;
            p7 = fmaf(a_, p7, b7); p8 = fmaf(a_, p8, b8);
        }
    }
    __syncthreads();
    float y7 = s1[g][lx], y8 = s2[g][lx];
    for (int i = 0; i < 64; ++i) {
        int y = y0 + i;
        float av = gy2[(long)y * 512 + x];
        float om = 1.f - av;
        y7 = fmaf(av, y7, om * h3[(long)y * 512 + x]);
        y8 = fmaf(av, y8, om * h4[(long)(511 - y) * 512 + x]);
        elt[(long)y * 512 + x] = fmaxf(hm[(long)y * 512 + x], fmaxf(y7, y8));
    }
}

// ---------------- launch ----------------
static inline int gs(long total, int bs) { return (int)((total + bs - 1) / bs); }

template <int K, int ACT, int CO, int XT>
static void launch_conv(const float* srcA, int ca, const float* srcB, int cb,
                        float* dst, int cout, const float* w, const float* b,
                        int H, int W, int N, cudaStream_t st = 0)
{
    const int BT = 128;
    int WXT = W / XT;
    int nblk = (H * WXT + BT - 1) / BT;
    int coG = (cout + CO - 1) / CO;
    int blocks = N * coG * nblk;
    int smem = (ca + cb) * K * K * CO * (int)sizeof(float);
    conv2d_pk<K, ACT, CO, XT><<<blocks, BT, smem, st>>>(srcA, ca, srcB, cb, dst, cout, w, b, H, W, N, nblk);
}

extern "C" void kernel_launch(void* const* d_in, const int* in_sizes, int n_in,
                              void* d_out, int out_size)
{
    const float* x    = (const float*)d_in[0];
    const float* w_s1 = (const float*)d_in[1];  const float* b_s1 = (const float*)d_in[2];
    const float* w_mc = (const float*)d_in[3];  const float* b_mc = (const float*)d_in[4];
    const float* w2   = (const float*)d_in[5];  const float* b2   = (const float*)d_in[6];
    const float* w3   = (const float*)d_in[7];  const float* b3   = (const float*)d_in[8];
    const float* w4   = (const float*)d_in[9];  const float* b4   = (const float*)d_in[10];
    const float* w5   = (const float*)d_in[11]; const float* b5   = (const float*)d_in[12];
    const float* w6   = (const float*)d_in[13]; const float* b6   = (const float*)d_in[14];
    const float* w6s  = (const float*)d_in[15]; const float* b6s  = (const float*)d_in[16];
    const float* w7   = (const float*)d_in[17]; const float* b7   = (const float*)d_in[18];
    const float* w8   = (const float*)d_in[19]; const float* b8   = (const float*)d_in[20];
    const float* w9   = (const float*)d_in[21]; const float* b9   = (const float*)d_in[22];
    const float* w10  = (const float*)d_in[23]; const float* b10  = (const float*)d_in[24];
    const float* w11  = (const float*)d_in[25]; const float* b11  = (const float*)d_in[26];
    float* out = (float*)d_out;

    float* pool = nullptr;
    cudaGetSymbolAddress((void**)&pool, g_pool);

    static const int SM9  = (32 * 408 + 32 * 272 + 16896 + 64) * 4;
    static const int SM10 = (16 * 408 + 16 * 272 + 16896 + 64) * 4;
    cudaFuncSetAttribute(conv3_wino<32, 2, 1, 1>, cudaFuncAttributeMaxDynamicSharedMemorySize, SM9);
    cudaFuncSetAttribute(conv3_wino<16, 1, 0, 0>, cudaFuncAttributeMaxDynamicSharedMemorySize, SM10);

    static cudaStream_t sideQ = nullptr;
    static cudaEvent_t evFork = nullptr, evJoin = nullptr;
    if (!sideQ) {
        cudaStreamCreateWithFlags(&sideQ, cudaStreamNonBlocking);
        cudaEventCreateWithFlags(&evFork, cudaEventDisableTiming);
        cudaEventCreateWithFlags(&evJoin, cudaEventDisableTiming);
    }

    const int BS = 256;
    const int N = 2;

    // ---- fork: branch A on sideQ ----
    cudaEventRecord(evFork, 0);
    cudaStreamWaitEvent(sideQ, evFork, 0);

    wino_filt<<<gs(64 * 32, BS), BS, 0, sideQ>>>(w9, pool + O_U9, 32);
    wino_filt<<<gs(64 * 16, BS), BS, 0, sideQ>>>(w10, pool + O_U10, 16);
    launch_conv<3, 0, 4, 8>(x, 3, nullptr, 0, pool + O_S1, 3, w_s1, b_s1, 512, 512, N, sideQ);
    maxpool_kernel<<<gs((long)N * 3 * 256 * 256, BS), BS, 0, sideQ>>>(pool + O_S1, pool + O_S2, 3, 256, 256, N);
    maxpool_kernel<<<gs((long)N * 3 * 128 * 128, BS), BS, 0, sideQ>>>(pool + O_S2, pool + O_S3, 3, 128, 128, N);
    maxpool_kernel<<<gs((long)N * 3 * 64 * 64, BS), BS, 0, sideQ>>>(pool + O_S3, pool + O_S4, 3, 64, 64, N);
    for (int n = 0; n < N; ++n)
        cudaMemcpyAsync(pool + O_MULTI + (long)n * 12 * PX, pool + O_S1 + (long)n * 3 * PX,
                        3 * PX * sizeof(float), cudaMemcpyDeviceToDevice, sideQ);
    upsample_kernel<<<gs((long)N * 3 * PX, BS), BS, 0, sideQ>>>(pool + O_S2, pool + O_MULTI + 3 * PX,
        3, 256, 256, 2, 3 * (PX / 4), 12 * PX, N);
    upsample_kernel<<<gs((long)N * 3 * PX, BS), BS, 0, sideQ>>>(pool + O_S3, pool + O_MULTI + 6 * PX,
        3, 128, 128, 4, 3 * (PX / 16), 12 * PX, N);
    upsample_kernel<<<gs((long)N * 3 * PX, BS), BS, 0, sideQ>>>(pool + O_S4, pool + O_MULTI + 9 * PX,
        3, 64, 64, 8, 3 * (PX / 64), 12 * PX, N);
    launch_conv<3, 0, 8, 8>(pool + O_MULTI, 12, nullptr, 0, pool + O_MS, 16, w_mc, b_mc, 512, 512, N, sideQ);
    cudaEventRecord(evJoin, sideQ);

    // ---- branch B: c2 + encoder/decoder ----
    launch_conv<5, 1, 8, 4>(x, 3, nullptr, 0, pool + O_C2, 16, w2, b2, 512, 512, N);
    maxpool_kernel<<<gs((long)N * 16 * 256 * 256, BS), BS>>>(pool + O_C2, pool + O_C2P, 16, 256, 256, N);
    launch_conv<3, 1, 8, 8>(pool + O_C2P, 16, nullptr, 0, pool + O_C3, 32, w3, b3, 256, 256, N);
    maxpool_kernel<<<gs((long)N * 32 * 128 * 128, BS), BS>>>(pool + O_C3, pool + O_C3P, 32, 128, 128, N);
    launch_conv<3, 1, 8, 8>(pool + O_C3P, 32, nullptr, 0, pool + O_C4, 32, w4, b4, 128, 128, N);
    maxpool_kernel<<<gs((long)N * 32 * 64 * 64, BS), BS>>>(pool + O_C4, pool + O_C4P, 32, 64, 64, N);
    launch_conv<3, 1, 8, 4>(pool + O_C4P, 32, nullptr, 0, pool + O_C5, 32, w5, b5, 64, 64, N);
    maxpool_kernel<<<gs((long)N * 32 * 32 * 32, BS), BS>>>(pool + O_C5, pool + O_C5P, 32, 32, 32, N);
    launch_conv<3, 1, 8, 4>(pool + O_C5P, 32, nullptr, 0, pool + O_C6, 64, w6, b6, 32, 32, N);
    upsample_kernel<<<gs((long)N * 64 * 64 * 64, BS), BS>>>(pool + O_C6, pool + O_C6U,
        64, 32, 32, 2, 64L * 32 * 32, 64L * 64 * 64, N);
    launch_conv<3, 1, 8, 4>(pool + O_C6U, 64, nullptr, 0, pool + O_C6S, 64, w6s, b6s, 64, 64, N);
    upsample_kernel<<<gs((long)N * 64 * 128 * 128, BS), BS>>>(pool + O_C6S, pool + O_C6RE,
        64, 64, 64, 2, 64L * 64 * 64, 64L * 128 * 128, N);
    launch_conv<3, 1, 8, 8>(pool + O_C6RE, 64, pool + O_C4, 32, pool + O_C7C, 32, w7, b7, 128, 128, N);
    upsample_kernel<<<gs((long)N * 32 * 256 * 256, BS), BS>>>(pool + O_C7C, pool + O_C7,
        32, 128, 128, 2, 32L * 128 * 128, 32L * 256 * 256, N);
    launch_conv<3, 1, 8, 8>(pool + O_C7, 32, pool + O_C3, 32, pool + O_C8C, 16, w8, b8, 256, 256, N);
    // c8 upsample fused into conv3_wino below

    // ---- join ----
    cudaStreamWaitEvent(0, evJoin, 0);

    {
        dim3 grid(8, 128, N);
        conv3_wino<32, 2, 1, 1><<<grid, 512, SM9>>>(pool + O_C8C, 16, pool + O_C2,
                                                    pool + O_U9, b9, pool + O_C9);
    }
    hscan_fused<<<2048, 256>>>();
    vscan_all<<<512, 256>>>();
    {
        dim3 grid(8, 128, N);
        conv3_wino<16, 1, 0, 0><<<grid, 512, SM10>>>(pool + O_ELT, 16, nullptr,
                                                     pool + O_U10, b10, pool + O_C10);
    }
    launch_conv<3, 1, 4, 8>(pool + O_C10, 64, nullptr, 0, out, 3, w11, b11, 512, 512, N);
}